// round 1
// baseline (speedup 1.0000x reference)
#include <cuda_runtime.h>
#include <cstdint>

// Problem constants
static constexpr int BDIM = 2;
static constexpr int NC   = 16384;
static constexpr int NF   = 65536;
static constexpr int CI   = 128;
static constexpr int CO   = 128;
static constexpr int EC   = 65536;
static constexpr int EF   = 262144;

// Scratch (device globals; no runtime allocation allowed)
__device__ float g_xf [(size_t)BDIM * NF * CI];        // unpool(x)            64MB
__device__ float g_hb [(size_t)BDIM * NF * CO];        // b-conv accumulator   64MB
__device__ float g_ha [(size_t)BDIM * NC * (CO / 2)];  // a-conv accumulator    8MB
__device__ float g_haf[(size_t)BDIM * NF * (CO / 2)];  // unpool(a-conv)       32MB

// ---------------------------------------------------------------------------
__global__ void zero_kernel(float4* __restrict__ p, int n4) {
    int i = blockIdx.x * blockDim.x + threadIdx.x;
    int stride = gridDim.x * blockDim.x;
    float4 z = make_float4(0.f, 0.f, 0.f, 0.f);
    for (; i < n4; i += stride) p[i] = z;
}

template <int C>
__global__ void unpool_kernel(const float* __restrict__ src, float* __restrict__ dst,
                              const int* __restrict__ idx, int nc, int nf) {
    const int c4n = C / 4;
    int total = BDIM * nc * c4n;
    int i = blockIdx.x * blockDim.x + threadIdx.x;
    int stride = gridDim.x * blockDim.x;
    for (; i < total; i += stride) {
        int c4 = i % c4n;
        int r  = i / c4n;           // b*nc + node
        int b  = r / nc;
        int nd = r - b * nc;
        int j  = idx[nd];
        reinterpret_cast<float4*>(dst)[(size_t)(b * nf + j) * c4n + c4] =
            reinterpret_cast<const float4*>(src)[(size_t)r * c4n + c4];
    }
}

// ---------------------------------------------------------------------------
// Fused edgeconv: gather -> 2-layer MLP -> LayerNorm -> atomic segment-sum.
// Block = 128 threads, tile = 32 edges. Weights fully resident in smem.
template <int CIN, int COUT>
__global__ void __launch_bounds__(128, 1)
edgeconv_kernel(const float* __restrict__ x, const int* __restrict__ ei,
                const float* __restrict__ W1, const float* __restrict__ b1,
                const float* __restrict__ W2, const float* __restrict__ b2,
                const float* __restrict__ gam, const float* __restrict__ bet,
                float* __restrict__ out, int E, int NROW) {
    constexpr int K1 = 2 * CIN;
    constexpr int P1 = K1 + 1;        // odd pitch -> conflict-free feat reads
    constexpr int P2 = COUT + 1;
    constexpr int NE = 32;            // edges per tile
    constexpr int JT = COUT / 16;     // out-cols per thread (8 or 4)
    constexpr int U  = COUT / 32;     // channels per lane in LN phase

    extern __shared__ float sm[];
    float* sW1 = sm;                          // K1*COUT
    float* sW2 = sW1 + K1 * COUT;             // COUT*COUT
    float* sb1 = sW2 + COUT * COUT;
    float* sb2 = sb1 + COUT;
    float* sg  = sb2 + COUT;
    float* sbt = sg + COUT;
    float* sF  = sbt + COUT;                  // NE*P1 scratch (feat / h1 / h2)
    int*  sdst = (int*)(sF + NE * P1);        // NE

    const int tid  = threadIdx.x;
    const int lane = tid & 31;
    const int warp = tid >> 5;
    const int ej   = tid & 7;                 // edge-tile index (0..7)
    const int jj   = tid >> 3;                // col-tile index (0..15)
    const int e0   = ej * 4;
    const int j0   = jj * JT;

    // Load weights once per block
    for (int i = tid; i < (K1 * COUT) / 4; i += 128)
        reinterpret_cast<float4*>(sW1)[i] = reinterpret_cast<const float4*>(W1)[i];
    for (int i = tid; i < (COUT * COUT) / 4; i += 128)
        reinterpret_cast<float4*>(sW2)[i] = reinterpret_cast<const float4*>(W2)[i];
    if (tid < COUT) {
        sb1[tid] = b1[tid]; sb2[tid] = b2[tid];
        sg[tid]  = gam[tid]; sbt[tid] = bet[tid];
    }

    const int total  = 2 * E;                 // B * E edge-instances
    const int ntiles = (total + NE - 1) / NE;

    for (int tile = blockIdx.x; tile < ntiles; tile += gridDim.x) {
        __syncthreads();   // protect smem scratch reuse across tiles / weight load

        // ---- gather: each warp loads 8 edges ----
        for (int r = 0; r < 8; ++r) {
            int e  = warp * 8 + r;
            int gi = tile * NE + e;
            bool valid = gi < total;
            int bb = 0, srcI = 0, dstI = 0;
            if (valid) {
                bb = gi / E;
                int ee = gi - bb * E;
                srcI = ei[ee];
                dstI = ei[E + ee];
            }
            if (lane == 0) sdst[e] = valid ? (bb * NROW + dstI) : -1;
            const float* xd = x + ((size_t)bb * NROW + dstI) * CIN;
            const float* xs = x + ((size_t)bb * NROW + srcI) * CIN;
            if (CIN == 128) {
                float4 d = valid ? reinterpret_cast<const float4*>(xd)[lane]
                                 : make_float4(0.f, 0.f, 0.f, 0.f);
                float4 s = valid ? reinterpret_cast<const float4*>(xs)[lane]
                                 : make_float4(0.f, 0.f, 0.f, 0.f);
                int c = lane * 4;
                float* f = sF + e * P1;
                f[c + 0] = d.x; f[c + 1] = d.y; f[c + 2] = d.z; f[c + 3] = d.w;
                f[CIN + c + 0] = s.x - d.x; f[CIN + c + 1] = s.y - d.y;
                f[CIN + c + 2] = s.z - d.z; f[CIN + c + 3] = s.w - d.w;
            } else {  // CIN == 64
                float2 d = valid ? reinterpret_cast<const float2*>(xd)[lane]
                                 : make_float2(0.f, 0.f);
                float2 s = valid ? reinterpret_cast<const float2*>(xs)[lane]
                                 : make_float2(0.f, 0.f);
                int c = lane * 2;
                float* f = sF + e * P1;
                f[c + 0] = d.x; f[c + 1] = d.y;
                f[CIN + c + 0] = s.x - d.x; f[CIN + c + 1] = s.y - d.y;
            }
        }
        __syncthreads();

        // ---- layer 1: h1 = relu(feat @ W1 + b1) ----
        float acc[4][JT];
        #pragma unroll
        for (int i = 0; i < 4; i++)
            #pragma unroll
            for (int t = 0; t < JT; t++) acc[i][t] = sb1[j0 + t];

        #pragma unroll 4
        for (int k = 0; k < K1; ++k) {
            float w[JT];
            #pragma unroll
            for (int t = 0; t < JT; t += 4) {
                float4 w4 = *reinterpret_cast<const float4*>(&sW1[k * COUT + j0 + t]);
                w[t] = w4.x; w[t + 1] = w4.y; w[t + 2] = w4.z; w[t + 3] = w4.w;
            }
            #pragma unroll
            for (int i = 0; i < 4; i++) {
                float f = sF[(e0 + i) * P1 + k];
                #pragma unroll
                for (int t = 0; t < JT; t++) acc[i][t] = fmaf(f, w[t], acc[i][t]);
            }
        }
        __syncthreads();   // feat dead; reuse scratch for h1
        #pragma unroll
        for (int i = 0; i < 4; i++)
            #pragma unroll
            for (int t = 0; t < JT; t++)
                sF[(e0 + i) * P2 + j0 + t] = fmaxf(acc[i][t], 0.f);
        __syncthreads();

        // ---- layer 2: h2 = h1 @ W2 + b2 ----
        #pragma unroll
        for (int i = 0; i < 4; i++)
            #pragma unroll
            for (int t = 0; t < JT; t++) acc[i][t] = sb2[j0 + t];

        #pragma unroll 4
        for (int k = 0; k < COUT; ++k) {
            float w[JT];
            #pragma unroll
            for (int t = 0; t < JT; t += 4) {
                float4 w4 = *reinterpret_cast<const float4*>(&sW2[k * COUT + j0 + t]);
                w[t] = w4.x; w[t + 1] = w4.y; w[t + 2] = w4.z; w[t + 3] = w4.w;
            }
            #pragma unroll
            for (int i = 0; i < 4; i++) {
                float f = sF[(e0 + i) * P2 + k];
                #pragma unroll
                for (int t = 0; t < JT; t++) acc[i][t] = fmaf(f, w[t], acc[i][t]);
            }
        }
        __syncthreads();   // h1 dead; reuse scratch for h2
        #pragma unroll
        for (int i = 0; i < 4; i++)
            #pragma unroll
            for (int t = 0; t < JT; t++)
                sF[(e0 + i) * P2 + j0 + t] = acc[i][t];
        __syncthreads();

        // ---- LayerNorm + atomic segment-sum: warp per edge ----
        for (int r = 0; r < 8; ++r) {
            int e = warp * 8 + r;
            int row = sdst[e];
            if (row < 0) continue;   // warp-uniform
            float v[U];
            float s = 0.f, sq = 0.f;
            #pragma unroll
            for (int u = 0; u < U; u++) {
                v[u] = sF[e * P2 + lane + 32 * u];
                s += v[u]; sq += v[u] * v[u];
            }
            #pragma unroll
            for (int o = 16; o > 0; o >>= 1) {
                s  += __shfl_xor_sync(0xffffffffu, s,  o);
                sq += __shfl_xor_sync(0xffffffffu, sq, o);
            }
            float mu  = s * (1.f / COUT);
            float var = sq * (1.f / COUT) - mu * mu;
            float rs  = rsqrtf(var + 1e-5f);
            #pragma unroll
            for (int u = 0; u < U; u++) {
                int c = lane + 32 * u;
                float val = (v[u] - mu) * rs * sg[c] + sbt[c];
                atomicAdd(&out[(size_t)row * COUT + c], val);
            }
        }
    }
}

// ---------------------------------------------------------------------------
__global__ void combine_kernel(float* __restrict__ out, const float* __restrict__ hb, int n4) {
    int i = blockIdx.x * blockDim.x + threadIdx.x;
    int stride = gridDim.x * blockDim.x;
    for (; i < n4; i += stride) {
        float4 a = reinterpret_cast<float4*>(out)[i];
        float4 b = reinterpret_cast<const float4*>(hb)[i];
        float4 r;
        r.x = a.x + b.x; r.x = r.x > 0.f ? r.x : 0.01f * r.x;
        r.y = a.y + b.y; r.y = r.y > 0.f ? r.y : 0.01f * r.y;
        r.z = a.z + b.z; r.z = r.z > 0.f ? r.z : 0.01f * r.z;
        r.w = a.w + b.w; r.w = r.w > 0.f ? r.w : 0.01f * r.w;
        reinterpret_cast<float4*>(out)[i] = r;
    }
}

// ---------------------------------------------------------------------------
static constexpr int smem_bytes(int CIN, int COUT) {
    int K1 = 2 * CIN, P1 = K1 + 1;
    return (K1 * COUT + COUT * COUT + 4 * COUT + 32 * P1) * 4 + 32 * 4;
}

extern "C" void kernel_launch(void* const* d_in, const int* in_sizes, int n_in,
                              void* d_out, int out_size) {
    (void)in_sizes; (void)n_in; (void)out_size;
    const float* x    = (const float*)d_in[0];
    const int*   idx  = (const int*)d_in[1];
    const int*   ei_c = (const int*)d_in[2];
    const int*   ei_f = (const int*)d_in[3];
    const float* sW1 = (const float*)d_in[4];
    const float* sb1 = (const float*)d_in[5];
    const float* sW2 = (const float*)d_in[6];
    const float* sb2 = (const float*)d_in[7];
    const float* sg  = (const float*)d_in[8];
    const float* sbt = (const float*)d_in[9];
    const float* aW1 = (const float*)d_in[10];
    const float* ab1 = (const float*)d_in[11];
    const float* aW2 = (const float*)d_in[12];
    const float* ab2 = (const float*)d_in[13];
    const float* ag  = (const float*)d_in[14];
    const float* abt = (const float*)d_in[15];
    const float* bW1 = (const float*)d_in[16];
    const float* bb1 = (const float*)d_in[17];
    const float* bW2 = (const float*)d_in[18];
    const float* bb2 = (const float*)d_in[19];
    const float* bg  = (const float*)d_in[20];
    const float* bbt = (const float*)d_in[21];
    float* out = (float*)d_out;

    float *xf, *hb, *ha, *haf;
    cudaGetSymbolAddress((void**)&xf,  g_xf);
    cudaGetSymbolAddress((void**)&hb,  g_hb);
    cudaGetSymbolAddress((void**)&ha,  g_ha);
    cudaGetSymbolAddress((void**)&haf, g_haf);

    constexpr int SM_S = smem_bytes(128, 128);  // 231680 B
    constexpr int SM_A = smem_bytes(128, 64);   // 115968 B
    constexpr int SM_B = smem_bytes(64, 128);   // 149760 B
    cudaFuncSetAttribute(edgeconv_kernel<128, 128>,
                         cudaFuncAttributeMaxDynamicSharedMemorySize, SM_S);
    cudaFuncSetAttribute(edgeconv_kernel<128, 64>,
                         cudaFuncAttributeMaxDynamicSharedMemorySize, SM_A);
    cudaFuncSetAttribute(edgeconv_kernel<64, 128>,
                         cudaFuncAttributeMaxDynamicSharedMemorySize, SM_B);

    // Zero scratch + output accumulators
    zero_kernel<<<512, 256>>>((float4*)xf,  BDIM * NF * CI / 4);
    zero_kernel<<<512, 256>>>((float4*)hb,  BDIM * NF * CO / 4);
    zero_kernel<<<128, 256>>>((float4*)ha,  BDIM * NC * 64 / 4);
    zero_kernel<<<256, 256>>>((float4*)haf, BDIM * NF * 64 / 4);
    zero_kernel<<<512, 256>>>((float4*)out, BDIM * NF * CO / 4);

    // xf = unpool(x)
    unpool_kernel<128><<<1024, 256>>>(x, xf, idx, NC, NF);

    // skip = edgeconv(xf, ei_f, s-params) -> accumulate into out
    edgeconv_kernel<128, 128><<<148, 128, SM_S>>>(
        xf, ei_f, sW1, sb1, sW2, sb2, sg, sbt, out, EF, NF);

    // h = edgeconv(x, ei_c, a-params) -> g_ha
    edgeconv_kernel<128, 64><<<148, 128, SM_A>>>(
        x, ei_c, aW1, ab1, aW2, ab2, ag, abt, ha, EC, NC);

    // haf = unpool(h)
    unpool_kernel<64><<<512, 256>>>(ha, haf, idx, NC, NF);

    // h = edgeconv(haf, ei_f, b-params) -> g_hb
    edgeconv_kernel<64, 128><<<148, 128, SM_B>>>(
        haf, ei_f, bW1, bb1, bW2, bb2, bg, bbt, hb, EF, NF);

    // out = leaky_relu(out + hb, 0.01)
    combine_kernel<<<512, 256>>>(out, hb, BDIM * NF * CO / 4);
}

// round 2
// speedup vs baseline: 1.7782x; 1.7782x over previous
#include <cuda_runtime.h>
#include <cstdint>

// Problem constants
static constexpr int BDIM = 2;
static constexpr int NC   = 16384;
static constexpr int NF   = 65536;
static constexpr int CI   = 128;
static constexpr int CO   = 128;
static constexpr int EC   = 65536;
static constexpr int EF   = 262144;

// Scratch (device globals; zero-initialized at module load; no runtime alloc)
__device__ float g_xf [(size_t)BDIM * NF * CI];        // unpool(x)   (non-idx rows stay 0 forever)
__device__ float g_hb [(size_t)BDIM * NF * CO];        // b-conv accumulator
__device__ float g_ha [(size_t)BDIM * NC * (CO / 2)];  // a-conv accumulator
__device__ float g_haf[(size_t)BDIM * NF * (CO / 2)];  // unpool(a-conv) (non-idx rows stay 0)
__device__ unsigned char g_mask[NF];                   // row in idx?
__device__ int   g_cntA[NF + 16];                      // A-class edge count per dst; [NF] = nComp
__device__ int   g_csrc[EF];                           // compacted non-A edges
__device__ int   g_cdst[EF];
__device__ float g_cs[CO];                             // constant LN vector, s-conv
__device__ float g_cb[CO];                             // constant LN vector, b-conv

// ---------------------------------------------------------------------------
// f32x2 packed math helpers (FFMA2 — ptxas won't auto-fuse; PTX required)
typedef unsigned long long u64;
__device__ __forceinline__ u64 pk2(float x) {
    u64 r; asm("mov.b64 %0,{%1,%1};" : "=l"(r) : "f"(x)); return r;
}
__device__ __forceinline__ void up2(u64 v, float& x, float& y) {
    asm("mov.b64 {%0,%1},%2;" : "=f"(x), "=f"(y) : "l"(v));
}
__device__ __forceinline__ u64 fma2(u64 a, u64 b, u64 c) {
    u64 d; asm("fma.rn.f32x2 %0,%1,%2,%3;" : "=l"(d) : "l"(a), "l"(b), "l"(c)); return d;
}

// ---------------------------------------------------------------------------
__global__ void zero_kernel(float4* __restrict__ p, int n4) {
    int i = blockIdx.x * blockDim.x + threadIdx.x;
    int stride = gridDim.x * blockDim.x;
    float4 z = make_float4(0.f, 0.f, 0.f, 0.f);
    for (; i < n4; i += stride) p[i] = z;
}

__global__ void mask_kernel(const int* __restrict__ idx, unsigned char* __restrict__ mask) {
    int i = blockIdx.x * blockDim.x + threadIdx.x;
    if (i < NC) mask[idx[i]] = 1;
}

// Classify ei_f edges: both endpoints zero-row -> count per dst; else compact.
__global__ void classify_kernel(const int* __restrict__ ei, const unsigned char* __restrict__ mask,
                                int* __restrict__ cntA, int* __restrict__ csrc,
                                int* __restrict__ cdst, int* __restrict__ ncomp) {
    int e = blockIdx.x * blockDim.x + threadIdx.x;
    if (e >= EF) return;
    int s = ei[e], d = ei[EF + e];
    bool zeroA = (!mask[s]) && (!mask[d]);
    if (zeroA) {
        atomicAdd(&cntA[d], 1);
    } else {
        unsigned act = __activemask();
        int lane = threadIdx.x & 31;
        int rank = __popc(act & ((1u << lane) - 1));
        int leader = __ffs(act) - 1;
        int base = 0;
        if (lane == leader) base = atomicAdd(ncomp, __popc(act));
        base = __shfl_sync(act, base, leader);
        int p = base + rank;
        csrc[p] = s;
        cdst[p] = d;
    }
}

// Constant vector for zero-feature edges: c = LN(relu(b1) @ W2 + b2)*g + bt
__global__ void constvec_kernel(const float* __restrict__ b1, const float* __restrict__ W2,
                                const float* __restrict__ b2, const float* __restrict__ g,
                                const float* __restrict__ bt, float* __restrict__ c) {
    int j = threadIdx.x;  // CO threads
    float acc = b2[j];
    #pragma unroll 4
    for (int k = 0; k < CO; k++) acc += fmaxf(b1[k], 0.f) * W2[k * CO + j];
    __shared__ float rs_[4], rq_[4];
    float s = acc, q = acc * acc;
    #pragma unroll
    for (int o = 16; o; o >>= 1) {
        s += __shfl_xor_sync(0xffffffffu, s, o);
        q += __shfl_xor_sync(0xffffffffu, q, o);
    }
    int warp = j >> 5, lane = j & 31;
    if (lane == 0) { rs_[warp] = s; rq_[warp] = q; }
    __syncthreads();
    float S = 0.f, Q = 0.f;
    #pragma unroll
    for (int w = 0; w < 4; w++) { S += rs_[w]; Q += rq_[w]; }
    float mu  = S * (1.f / CO);
    float var = Q * (1.f / CO) - mu * mu;
    c[j] = (acc - mu) * rsqrtf(var + 1e-5f) * g[j] + bt[j];
}

template <int C>
__global__ void unpool_kernel(const float* __restrict__ src, float* __restrict__ dst,
                              const int* __restrict__ idx, int nc, int nf) {
    const int c4n = C / 4;
    int total = BDIM * nc * c4n;
    int i = blockIdx.x * blockDim.x + threadIdx.x;
    int stride = gridDim.x * blockDim.x;
    for (; i < total; i += stride) {
        int c4 = i % c4n;
        int r  = i / c4n;
        int b  = r / nc;
        int nd = r - b * nc;
        int j  = idx[nd];
        reinterpret_cast<float4*>(dst)[(size_t)(b * nf + j) * c4n + c4] =
            reinterpret_cast<const float4*>(src)[(size_t)r * c4n + c4];
    }
}

// ---------------------------------------------------------------------------
// Fused edgeconv: gather -> MLP (f32x2 FMA) -> LayerNorm -> atomic scatter.
// Block = 128 threads, tile = 32 edges. Weights resident in smem.
template <int CIN, int COUT, bool NCOMP>
__global__ void __launch_bounds__(128, 1)
edgeconv_kernel(const float* __restrict__ x,
                const int* __restrict__ srcA, const int* __restrict__ dstA,
                const float* __restrict__ W1, const float* __restrict__ b1,
                const float* __restrict__ W2, const float* __restrict__ b2,
                const float* __restrict__ gam, const float* __restrict__ bet,
                float* __restrict__ out, int E, int NROW,
                const int* __restrict__ ncomp) {
    constexpr int K1  = 2 * CIN;
    constexpr int P1  = K1 + 1;
    constexpr int P2  = COUT + 1;
    constexpr int NE  = 32;
    constexpr int JT  = COUT / 16;    // cols per thread (8 or 4)
    constexpr int JT2 = JT / 2;       // packed col-pairs per thread
    constexpr int U   = COUT / 32;

    extern __shared__ float sm[];
    float* sW1 = sm;
    float* sW2 = sW1 + K1 * COUT;
    float* sb1 = sW2 + COUT * COUT;
    float* sb2 = sb1 + COUT;
    float* sg  = sb2 + COUT;
    float* sbt = sg + COUT;
    float* sF  = sbt + COUT;
    int*  sdst = (int*)(sF + NE * P1);

    const int tid  = threadIdx.x;
    const int lane = tid & 31;
    const int warp = tid >> 5;
    const int ej   = tid & 7;
    const int jj   = tid >> 3;
    const int e0   = ej * 4;
    const int j0   = jj * JT;

    for (int i = tid; i < (K1 * COUT) / 4; i += 128)
        reinterpret_cast<float4*>(sW1)[i] = reinterpret_cast<const float4*>(W1)[i];
    for (int i = tid; i < (COUT * COUT) / 4; i += 128)
        reinterpret_cast<float4*>(sW2)[i] = reinterpret_cast<const float4*>(W2)[i];
    if (tid < COUT) {
        sb1[tid] = b1[tid]; sb2[tid] = b2[tid];
        sg[tid]  = gam[tid]; sbt[tid] = bet[tid];
    }

    int Eeff;
    if (NCOMP) Eeff = *ncomp; else Eeff = E;
    const int total  = 2 * Eeff;
    const int ntiles = (total + NE - 1) / NE;

    for (int tile = blockIdx.x; tile < ntiles; tile += gridDim.x) {
        __syncthreads();

        // ---- gather ----
        for (int r = 0; r < 8; ++r) {
            int e  = warp * 8 + r;
            int gi = tile * NE + e;
            bool valid = gi < total;
            int bb = 0, srcI = 0, dstI = 0;
            if (valid) {
                bb = (gi >= Eeff) ? 1 : 0;
                int ee = gi - bb * Eeff;
                srcI = srcA[ee];
                dstI = dstA[ee];
            }
            if (lane == 0) sdst[e] = valid ? (bb * NROW + dstI) : -1;
            const float* xd = x + ((size_t)bb * NROW + dstI) * CIN;
            const float* xs = x + ((size_t)bb * NROW + srcI) * CIN;
            if (CIN == 128) {
                float4 d = valid ? reinterpret_cast<const float4*>(xd)[lane]
                                 : make_float4(0.f, 0.f, 0.f, 0.f);
                float4 s = valid ? reinterpret_cast<const float4*>(xs)[lane]
                                 : make_float4(0.f, 0.f, 0.f, 0.f);
                int c = lane * 4;
                float* f = sF + e * P1;
                f[c + 0] = d.x; f[c + 1] = d.y; f[c + 2] = d.z; f[c + 3] = d.w;
                f[CIN + c + 0] = s.x - d.x; f[CIN + c + 1] = s.y - d.y;
                f[CIN + c + 2] = s.z - d.z; f[CIN + c + 3] = s.w - d.w;
            } else {
                float2 d = valid ? reinterpret_cast<const float2*>(xd)[lane]
                                 : make_float2(0.f, 0.f);
                float2 s = valid ? reinterpret_cast<const float2*>(xs)[lane]
                                 : make_float2(0.f, 0.f);
                int c = lane * 2;
                float* f = sF + e * P1;
                f[c + 0] = d.x; f[c + 1] = d.y;
                f[CIN + c + 0] = s.x - d.x; f[CIN + c + 1] = s.y - d.y;
            }
        }
        __syncthreads();

        // ---- layer 1: h1 = relu(feat @ W1 + b1), f32x2 packed ----
        u64 acc[4][JT2];
        #pragma unroll
        for (int t = 0; t < JT2; t++) {
            u64 bv = *reinterpret_cast<const u64*>(&sb1[j0 + 2 * t]);
            #pragma unroll
            for (int i = 0; i < 4; i++) acc[i][t] = bv;
        }
        #pragma unroll 2
        for (int k = 0; k < K1; ++k) {
            u64 w[JT2];
            if constexpr (JT2 == 4) {
                ulonglong2 w01 = *reinterpret_cast<const ulonglong2*>(&sW1[k * COUT + j0]);
                ulonglong2 w23 = *reinterpret_cast<const ulonglong2*>(&sW1[k * COUT + j0 + 4]);
                w[0] = w01.x; w[1] = w01.y; w[2] = w23.x; w[3] = w23.y;
            } else {
                ulonglong2 w01 = *reinterpret_cast<const ulonglong2*>(&sW1[k * COUT + j0]);
                w[0] = w01.x; w[1] = w01.y;
            }
            #pragma unroll
            for (int i = 0; i < 4; i++) {
                u64 f2 = pk2(sF[(e0 + i) * P1 + k]);
                #pragma unroll
                for (int t = 0; t < JT2; t++) acc[i][t] = fma2(f2, w[t], acc[i][t]);
            }
        }
        __syncthreads();
        #pragma unroll
        for (int i = 0; i < 4; i++)
            #pragma unroll
            for (int t = 0; t < JT2; t++) {
                float a, b;
                up2(acc[i][t], a, b);
                sF[(e0 + i) * P2 + j0 + 2 * t]     = fmaxf(a, 0.f);
                sF[(e0 + i) * P2 + j0 + 2 * t + 1] = fmaxf(b, 0.f);
            }
        __syncthreads();

        // ---- layer 2: h2 = h1 @ W2 + b2 ----
        #pragma unroll
        for (int t = 0; t < JT2; t++) {
            u64 bv = *reinterpret_cast<const u64*>(&sb2[j0 + 2 * t]);
            #pragma unroll
            for (int i = 0; i < 4; i++) acc[i][t] = bv;
        }
        #pragma unroll 2
        for (int k = 0; k < COUT; ++k) {
            u64 w[JT2];
            if constexpr (JT2 == 4) {
                ulonglong2 w01 = *reinterpret_cast<const ulonglong2*>(&sW2[k * COUT + j0]);
                ulonglong2 w23 = *reinterpret_cast<const ulonglong2*>(&sW2[k * COUT + j0 + 4]);
                w[0] = w01.x; w[1] = w01.y; w[2] = w23.x; w[3] = w23.y;
            } else {
                ulonglong2 w01 = *reinterpret_cast<const ulonglong2*>(&sW2[k * COUT + j0]);
                w[0] = w01.x; w[1] = w01.y;
            }
            #pragma unroll
            for (int i = 0; i < 4; i++) {
                u64 f2 = pk2(sF[(e0 + i) * P2 + k]);
                #pragma unroll
                for (int t = 0; t < JT2; t++) acc[i][t] = fma2(f2, w[t], acc[i][t]);
            }
        }
        __syncthreads();
        #pragma unroll
        for (int i = 0; i < 4; i++)
            #pragma unroll
            for (int t = 0; t < JT2; t++) {
                float a, b;
                up2(acc[i][t], a, b);
                sF[(e0 + i) * P2 + j0 + 2 * t]     = a;
                sF[(e0 + i) * P2 + j0 + 2 * t + 1] = b;
            }
        __syncthreads();

        // ---- LayerNorm + atomic segment-sum (warp per edge) ----
        for (int r = 0; r < 8; ++r) {
            int e = warp * 8 + r;
            int row = sdst[e];
            if (row < 0) continue;
            float v[U];
            float s = 0.f, sq = 0.f;
            #pragma unroll
            for (int u = 0; u < U; u++) {
                v[u] = sF[e * P2 + lane + 32 * u];
                s += v[u]; sq += v[u] * v[u];
            }
            #pragma unroll
            for (int o = 16; o > 0; o >>= 1) {
                s  += __shfl_xor_sync(0xffffffffu, s,  o);
                sq += __shfl_xor_sync(0xffffffffu, sq, o);
            }
            float mu  = s * (1.f / COUT);
            float var = sq * (1.f / COUT) - mu * mu;
            float rs  = rsqrtf(var + 1e-5f);
            #pragma unroll
            for (int u = 0; u < U; u++) {
                int c = lane + 32 * u;
                float val = (v[u] - mu) * rs * sg[c] + sbt[c];
                atomicAdd(&out[(size_t)row * COUT + c], val);
            }
        }
    }
}

// ---------------------------------------------------------------------------
// out = leaky_relu(out + hb + countA[n]*(cs+cb), 0.01)
__global__ void combine_kernel(float* __restrict__ out, const float* __restrict__ hb,
                               const int* __restrict__ cntA,
                               const float* __restrict__ cs, const float* __restrict__ cb) {
    const int c4n = CO / 4;
    int total = BDIM * NF * c4n;
    int i = blockIdx.x * blockDim.x + threadIdx.x;
    int stride = gridDim.x * blockDim.x;
    for (; i < total; i += stride) {
        int j4 = i % c4n;
        int n  = (i / c4n) % NF;
        float cnt = (float)cntA[n];
        float4 a = reinterpret_cast<float4*>(out)[i];
        float4 b = reinterpret_cast<const float4*>(hb)[i];
        float4 s = reinterpret_cast<const float4*>(cs)[j4];
        float4 t = reinterpret_cast<const float4*>(cb)[j4];
        float4 r;
        r.x = a.x + b.x + cnt * (s.x + t.x); r.x = r.x > 0.f ? r.x : 0.01f * r.x;
        r.y = a.y + b.y + cnt * (s.y + t.y); r.y = r.y > 0.f ? r.y : 0.01f * r.y;
        r.z = a.z + b.z + cnt * (s.z + t.z); r.z = r.z > 0.f ? r.z : 0.01f * r.z;
        r.w = a.w + b.w + cnt * (s.w + t.w); r.w = r.w > 0.f ? r.w : 0.01f * r.w;
        reinterpret_cast<float4*>(out)[i] = r;
    }
}

// ---------------------------------------------------------------------------
static constexpr int smem_bytes(int CIN, int COUT) {
    int K1 = 2 * CIN, P1 = K1 + 1;
    return (K1 * COUT + COUT * COUT + 4 * COUT + 32 * P1) * 4 + 32 * 4;
}

extern "C" void kernel_launch(void* const* d_in, const int* in_sizes, int n_in,
                              void* d_out, int out_size) {
    (void)in_sizes; (void)n_in; (void)out_size;
    const float* x    = (const float*)d_in[0];
    const int*   idx  = (const int*)d_in[1];
    const int*   ei_c = (const int*)d_in[2];
    const int*   ei_f = (const int*)d_in[3];
    const float* sW1 = (const float*)d_in[4];
    const float* sb1 = (const float*)d_in[5];
    const float* sW2 = (const float*)d_in[6];
    const float* sb2 = (const float*)d_in[7];
    const float* sg  = (const float*)d_in[8];
    const float* sbt = (const float*)d_in[9];
    const float* aW1 = (const float*)d_in[10];
    const float* ab1 = (const float*)d_in[11];
    const float* aW2 = (const float*)d_in[12];
    const float* ab2 = (const float*)d_in[13];
    const float* ag  = (const float*)d_in[14];
    const float* abt = (const float*)d_in[15];
    const float* bW1 = (const float*)d_in[16];
    const float* bb1 = (const float*)d_in[17];
    const float* bW2 = (const float*)d_in[18];
    const float* bb2 = (const float*)d_in[19];
    const float* bg  = (const float*)d_in[20];
    const float* bbt = (const float*)d_in[21];
    float* out = (float*)d_out;

    float *xf, *hb, *ha, *haf, *cs, *cb;
    unsigned char* mask;
    int *cntA, *csrc, *cdst;
    cudaGetSymbolAddress((void**)&xf,   g_xf);
    cudaGetSymbolAddress((void**)&hb,   g_hb);
    cudaGetSymbolAddress((void**)&ha,   g_ha);
    cudaGetSymbolAddress((void**)&haf,  g_haf);
    cudaGetSymbolAddress((void**)&mask, g_mask);
    cudaGetSymbolAddress((void**)&cntA, g_cntA);
    cudaGetSymbolAddress((void**)&csrc, g_csrc);
    cudaGetSymbolAddress((void**)&cdst, g_cdst);
    cudaGetSymbolAddress((void**)&cs,   g_cs);
    cudaGetSymbolAddress((void**)&cb,   g_cb);
    int* ncomp = cntA + NF;

    constexpr int SM_S = smem_bytes(128, 128);
    constexpr int SM_A = smem_bytes(128, 64);
    constexpr int SM_B = smem_bytes(64, 128);
    cudaFuncSetAttribute(edgeconv_kernel<128, 128, true>,
                         cudaFuncAttributeMaxDynamicSharedMemorySize, SM_S);
    cudaFuncSetAttribute(edgeconv_kernel<128, 64, false>,
                         cudaFuncAttributeMaxDynamicSharedMemorySize, SM_A);
    cudaFuncSetAttribute(edgeconv_kernel<64, 128, true>,
                         cudaFuncAttributeMaxDynamicSharedMemorySize, SM_B);

    // Zero accumulators + classification state (xf/haf stay zero: only idx rows
    // are ever written, with idempotent values per launch)
    zero_kernel<<<512, 256>>>((float4*)hb,  BDIM * NF * CO / 4);
    zero_kernel<<<128, 256>>>((float4*)ha,  BDIM * NC * 64 / 4);
    zero_kernel<<<512, 256>>>((float4*)out, BDIM * NF * CO / 4);
    zero_kernel<<<32, 256>>>((float4*)cntA, (NF + 16) / 4);

    // Build membership mask + classify/compact fine-graph edges
    mask_kernel<<<NC / 256, 256>>>(idx, mask);
    classify_kernel<<<EF / 256, 256>>>(ei_f, mask, cntA, csrc, cdst, ncomp);

    // Constant vectors for zero-feature edges
    constvec_kernel<<<1, CO>>>(sb1, sW2, sb2, sg, sbt, cs);
    constvec_kernel<<<1, CO>>>(bb1, bW2, bb2, bg, bbt, cb);

    // xf = unpool(x)
    unpool_kernel<128><<<1024, 256>>>(x, xf, idx, NC, NF);

    // skip = edgeconv(xf, compacted ei_f, s-params) -> out
    edgeconv_kernel<128, 128, true><<<148, 128, SM_S>>>(
        xf, csrc, cdst, sW1, sb1, sW2, sb2, sg, sbt, out, 0, NF, ncomp);

    // h = edgeconv(x, ei_c, a-params) -> ha
    edgeconv_kernel<128, 64, false><<<148, 128, SM_A>>>(
        x, ei_c, ei_c + EC, aW1, ab1, aW2, ab2, ag, abt, ha, EC, NC, nullptr);

    // haf = unpool(h)
    unpool_kernel<64><<<512, 256>>>(ha, haf, idx, NC, NF);

    // h = edgeconv(haf, compacted ei_f, b-params) -> hb
    edgeconv_kernel<64, 128, true><<<148, 128, SM_B>>>(
        haf, csrc, cdst, bW1, bb1, bW2, bb2, bg, bbt, hb, 0, NF, ncomp);

    // out = leaky_relu(out + hb + cntA*(cs+cb))
    combine_kernel<<<512, 256>>>(out, hb, cntA, cs, cb);
}

// round 3
// speedup vs baseline: 2.4464x; 1.3758x over previous
#include <cuda_runtime.h>
#include <cstdint>

// Problem constants
static constexpr int BDIM = 2;
static constexpr int NC   = 16384;
static constexpr int NF   = 65536;
static constexpr int CI   = 128;
static constexpr int CO   = 128;
static constexpr int EC   = 65536;
static constexpr int EF   = 262144;

// Scratch (device globals; zero-initialized at module load)
__device__ float g_xf [(size_t)BDIM * NF * CI];        // unpool(x): non-idx rows stay 0
__device__ float g_hb [(size_t)BDIM * NF * CO];        // s+b conv accumulator
__device__ float g_ha [(size_t)BDIM * NC * (CO / 2)];  // a-conv accumulator
__device__ float g_haf[(size_t)BDIM * NF * (CO / 2)];  // unpool(a-conv): non-idx rows stay 0
__device__ unsigned char g_mask[NF];
__device__ int   g_cntA[NF + 16];                      // [NF] = nComp
__device__ int   g_csrc[EF];
__device__ int   g_cdst[EF];
__device__ float g_cs[CO];
__device__ float g_cb[CO];
__device__ float g_w1s[2 * CI * CO];                   // transformed W1 (s)
__device__ float g_w1a[2 * CI * (CO / 2)];             // transformed W1 (a)
__device__ float g_w1b[CI * CO];                       // transformed W1 (b)

// ---------------------------------------------------------------------------
typedef unsigned long long u64;
__device__ __forceinline__ u64 pk2(float x) {
    u64 r; asm("mov.b64 %0,{%1,%1};" : "=l"(r) : "f"(x)); return r;
}
__device__ __forceinline__ void up2(u64 v, float& x, float& y) {
    asm("mov.b64 {%0,%1},%2;" : "=f"(x), "=f"(y) : "l"(v));
}
__device__ __forceinline__ u64 fma2(u64 a, u64 b, u64 c) {
    u64 d; asm("fma.rn.f32x2 %0,%1,%2,%3;" : "=l"(d) : "l"(a), "l"(b), "l"(c)); return d;
}

// ---------------------------------------------------------------------------
__global__ void zero_kernel(float4* __restrict__ p, int n4) {
    int i = blockIdx.x * blockDim.x + threadIdx.x;
    int stride = gridDim.x * blockDim.x;
    float4 z = make_float4(0.f, 0.f, 0.f, 0.f);
    for (; i < n4; i += stride) p[i] = z;
}

__global__ void mask_kernel(const int* __restrict__ idx, unsigned char* __restrict__ mask) {
    int i = blockIdx.x * blockDim.x + threadIdx.x;
    if (i < NC) mask[idx[i]] = 1;
}

__global__ void classify_kernel(const int* __restrict__ ei, const unsigned char* __restrict__ mask,
                                int* __restrict__ cntA, int* __restrict__ csrc,
                                int* __restrict__ cdst, int* __restrict__ ncomp) {
    int e = blockIdx.x * blockDim.x + threadIdx.x;
    if (e >= EF) return;
    int s = ei[e], d = ei[EF + e];
    bool zeroA = (!mask[s]) && (!mask[d]);
    if (zeroA) {
        atomicAdd(&cntA[d], 1);
    } else {
        unsigned act = __activemask();
        int lane = threadIdx.x & 31;
        int rank = __popc(act & ((1u << lane) - 1));
        int leader = __ffs(act) - 1;
        int base = 0;
        if (lane == leader) base = atomicAdd(ncomp, __popc(act));
        base = __shfl_sync(act, base, leader);
        csrc[base + rank] = s;
        cdst[base + rank] = d;
    }
}

// W1t: rows [0,cin) = W1a - W1b ; rows [cin,2cin) = W1b
__global__ void prepW1_kernel(const float* __restrict__ W1, float* __restrict__ W1t,
                              int cin, int cout) {
    int i = blockIdx.x * blockDim.x + threadIdx.x;
    int n = cin * cout;
    if (i >= n) return;
    float top = W1[i];
    float bot = W1[n + i];
    W1t[i]     = top - bot;
    W1t[n + i] = bot;
}

__global__ void constvec_kernel(const float* __restrict__ b1, const float* __restrict__ W2,
                                const float* __restrict__ b2, const float* __restrict__ g,
                                const float* __restrict__ bt, float* __restrict__ c) {
    int j = threadIdx.x;  // CO threads
    float acc = b2[j];
    #pragma unroll 4
    for (int k = 0; k < CO; k++) acc += fmaxf(b1[k], 0.f) * W2[k * CO + j];
    __shared__ float rs_[4], rq_[4];
    float s = acc, qv = acc * acc;
    #pragma unroll
    for (int o = 16; o; o >>= 1) {
        s  += __shfl_xor_sync(0xffffffffu, s, o);
        qv += __shfl_xor_sync(0xffffffffu, qv, o);
    }
    int warp = j >> 5, lane = j & 31;
    if (lane == 0) { rs_[warp] = s; rq_[warp] = qv; }
    __syncthreads();
    float S = 0.f, Q = 0.f;
    #pragma unroll
    for (int w = 0; w < 4; w++) { S += rs_[w]; Q += rq_[w]; }
    float mu  = S * (1.f / CO);
    float var = Q * (1.f / CO) - mu * mu;
    c[j] = (acc - mu) * rsqrtf(var + 1e-5f) * g[j] + bt[j];
}

template <int C>
__global__ void unpool_kernel(const float* __restrict__ src, float* __restrict__ dst,
                              const int* __restrict__ idx, int nc, int nf) {
    const int c4n = C / 4;
    int total = BDIM * nc * c4n;
    int i = blockIdx.x * blockDim.x + threadIdx.x;
    int stride = gridDim.x * blockDim.x;
    for (; i < total; i += stride) {
        int c4 = i % c4n;
        int r  = i / c4n;
        int b  = r / nc;
        int nd = r - b * nc;
        int j  = idx[nd];
        reinterpret_cast<float4*>(dst)[(size_t)(b * nf + j) * c4n + c4] =
            reinterpret_cast<const float4*>(src)[(size_t)r * c4n + c4];
    }
}

// ---------------------------------------------------------------------------
// Fused edgeconv: pipelined gather -> MLP (f32x2) -> LayerNorm -> vector atomics.
// 256 threads, tile = 32 edges. feat = [xd, xs] raw (W1 pre-transformed).
template <int CIN, int COUT, bool NCOMP>
__global__ void __launch_bounds__(256, 1)
edgeconv_kernel(const float* __restrict__ x,
                const int* __restrict__ srcA, const int* __restrict__ dstA,
                const float* __restrict__ W1, const float* __restrict__ b1,
                const float* __restrict__ W2, const float* __restrict__ b2,
                const float* __restrict__ gam, const float* __restrict__ bet,
                float* __restrict__ out, int E, int NROW,
                const int* __restrict__ ncomp) {
    constexpr int K1  = 2 * CIN;
    constexpr int P1  = K1 + 1;           // odd pitch: conflict-free feat reads
    constexpr int P2  = COUT + 4;         // 16B-aligned rows for LN vector loads
    constexpr int NE  = 32;
    constexpr int JT  = COUT / 16;        // cols per thread (8 or 4)
    constexpr int JT2 = JT / 2;
    constexpr int NPF = CIN / 16;         // float4 prefetch regs per thread
    constexpr int PF  = (P1 > P2) ? P1 : P2;

    extern __shared__ float sm[];
    float* sW1 = sm;                              // K1*COUT
    float* sW2 = sW1 + K1 * COUT;                 // COUT*COUT
    float* sb1 = sW2 + COUT * COUT;
    float* sb2 = sb1 + COUT;
    float* sg  = sb2 + COUT;
    float* sbt = sg + COUT;
    float* sF  = sbt + COUT;                      // NE*PF (feat, then h aliased)
    int*  sdst = (int*)(sF + NE * PF);

    const int tid  = threadIdx.x;
    const int lane = tid & 31;
    const int warp = tid >> 5;
    // gather mapping: 64 rows (32 edges x {xd,xs}), 4 threads per row
    const int grow = tid >> 2;
    const int q    = tid & 3;
    const int ge   = grow >> 1;
    const int gh   = grow & 1;                    // 0 = xd(dst), 1 = xs(src)
    // gemm mapping
    const int eh   = tid & 15;                    // edges eh, eh+16
    const int jg   = tid >> 4;
    const int j0   = jg * JT;

    // Load weights once per block
    for (int i = tid; i < (K1 * COUT) / 4; i += 256)
        reinterpret_cast<float4*>(sW1)[i] = reinterpret_cast<const float4*>(W1)[i];
    for (int i = tid; i < (COUT * COUT) / 4; i += 256)
        reinterpret_cast<float4*>(sW2)[i] = reinterpret_cast<const float4*>(W2)[i];
    if (tid < COUT) {
        sb1[tid] = b1[tid]; sb2[tid] = b2[tid];
        sg[tid]  = gam[tid]; sbt[tid] = bet[tid];
    }

    int Eeff = NCOMP ? *ncomp : E;
    const int total  = 2 * Eeff;
    const int ntiles = (total + NE - 1) / NE;

    float4 pf[NPF];
    int pdst = -1;

    // prefetch data for a tile into registers
    auto fetch = [&](int tile) {
        pdst = -1;
        int gi = tile * NE + ge;
        if (tile < ntiles && gi < total) {
            int bb = (gi >= Eeff) ? 1 : 0;
            int ee = gi - bb * Eeff;
            int node = gh ? srcA[ee] : dstA[ee];
            int row  = bb * NROW + node;
            const float4* g = reinterpret_cast<const float4*>(x + (size_t)row * CIN);
            #pragma unroll
            for (int u = 0; u < NPF; u++) pf[u] = g[q + 4 * u];
            if (!gh) pdst = row;
        } else {
            #pragma unroll
            for (int u = 0; u < NPF; u++) pf[u] = make_float4(0.f, 0.f, 0.f, 0.f);
        }
    };

    if (blockIdx.x < ntiles) fetch(blockIdx.x);

    for (int tile = blockIdx.x; tile < ntiles; tile += gridDim.x) {
        __syncthreads();  // S1: previous tile fully consumed

        // ---- store prefetched feat ----
        {
            float* frow = sF + ge * P1 + gh * CIN;
            #pragma unroll
            for (int u = 0; u < NPF; u++) {
                int k0 = (q + 4 * u) * 4;
                frow[k0 + 0] = pf[u].x; frow[k0 + 1] = pf[u].y;
                frow[k0 + 2] = pf[u].z; frow[k0 + 3] = pf[u].w;
            }
            if (q == 0 && gh == 0) sdst[ge] = pdst;
        }
        __syncthreads();  // S2

        // ---- layer 1: h1 = relu(feat @ W1t + b1) ----
        u64 acc[2][JT2];
        #pragma unroll
        for (int t = 0; t < JT2; t++) {
            u64 bv = *reinterpret_cast<const u64*>(&sb1[j0 + 2 * t]);
            acc[0][t] = bv; acc[1][t] = bv;
        }
        #pragma unroll 2
        for (int k = 0; k < K1; ++k) {
            u64 w[JT2];
            if constexpr (JT2 == 4) {
                ulonglong2 w01 = *reinterpret_cast<const ulonglong2*>(&sW1[k * COUT + j0]);
                ulonglong2 w23 = *reinterpret_cast<const ulonglong2*>(&sW1[k * COUT + j0 + 4]);
                w[0] = w01.x; w[1] = w01.y; w[2] = w23.x; w[3] = w23.y;
            } else {
                ulonglong2 w01 = *reinterpret_cast<const ulonglong2*>(&sW1[k * COUT + j0]);
                w[0] = w01.x; w[1] = w01.y;
            }
            u64 f0 = pk2(sF[eh * P1 + k]);
            u64 f1 = pk2(sF[(eh + 16) * P1 + k]);
            #pragma unroll
            for (int t = 0; t < JT2; t++) {
                acc[0][t] = fma2(f0, w[t], acc[0][t]);
                acc[1][t] = fma2(f1, w[t], acc[1][t]);
            }
        }
        __syncthreads();  // S3: feat dead

        // ---- write h1 (relu), vectorized ----
        #pragma unroll
        for (int i = 0; i < 2; i++) {
            float v[JT];
            #pragma unroll
            for (int t = 0; t < JT2; t++) up2(acc[i][t], v[2 * t], v[2 * t + 1]);
            float* hrow = sF + (eh + 16 * i) * P2 + j0;
            #pragma unroll
            for (int t = 0; t < JT; t += 4) {
                float4 h4 = make_float4(fmaxf(v[t], 0.f), fmaxf(v[t + 1], 0.f),
                                        fmaxf(v[t + 2], 0.f), fmaxf(v[t + 3], 0.f));
                *reinterpret_cast<float4*>(hrow + t) = h4;
            }
        }
        __syncthreads();  // S4

        // prefetch next tile (hidden under layer 2)
        fetch(tile + gridDim.x);

        // ---- layer 2: h2 = h1 @ W2 + b2 ----
        #pragma unroll
        for (int t = 0; t < JT2; t++) {
            u64 bv = *reinterpret_cast<const u64*>(&sb2[j0 + 2 * t]);
            acc[0][t] = bv; acc[1][t] = bv;
        }
        #pragma unroll 2
        for (int k = 0; k < COUT; ++k) {
            u64 w[JT2];
            if constexpr (JT2 == 4) {
                ulonglong2 w01 = *reinterpret_cast<const ulonglong2*>(&sW2[k * COUT + j0]);
                ulonglong2 w23 = *reinterpret_cast<const ulonglong2*>(&sW2[k * COUT + j0 + 4]);
                w[0] = w01.x; w[1] = w01.y; w[2] = w23.x; w[3] = w23.y;
            } else {
                ulonglong2 w01 = *reinterpret_cast<const ulonglong2*>(&sW2[k * COUT + j0]);
                w[0] = w01.x; w[1] = w01.y;
            }
            u64 f0 = pk2(sF[eh * P2 + k]);
            u64 f1 = pk2(sF[(eh + 16) * P2 + k]);
            #pragma unroll
            for (int t = 0; t < JT2; t++) {
                acc[0][t] = fma2(f0, w[t], acc[0][t]);
                acc[1][t] = fma2(f1, w[t], acc[1][t]);
            }
        }
        __syncthreads();  // S5: h1 dead

        // ---- write h2 ----
        #pragma unroll
        for (int i = 0; i < 2; i++) {
            float v[JT];
            #pragma unroll
            for (int t = 0; t < JT2; t++) up2(acc[i][t], v[2 * t], v[2 * t + 1]);
            float* hrow = sF + (eh + 16 * i) * P2 + j0;
            #pragma unroll
            for (int t = 0; t < JT; t += 4)
                *reinterpret_cast<float4*>(hrow + t) =
                    make_float4(v[t], v[t + 1], v[t + 2], v[t + 3]);
        }
        __syncthreads();  // S6

        // ---- LayerNorm + vector atomic scatter (warp per edge) ----
        #pragma unroll
        for (int rr = 0; rr < 4; ++rr) {
            int e = warp + 8 * rr;
            int row = sdst[e];
            if (row < 0) continue;   // warp-uniform
            if constexpr (COUT == 128) {
                float4 v = *reinterpret_cast<const float4*>(&sF[e * P2 + lane * 4]);
                float s  = v.x + v.y + v.z + v.w;
                float sq = v.x * v.x + v.y * v.y + v.z * v.z + v.w * v.w;
                #pragma unroll
                for (int o = 16; o > 0; o >>= 1) {
                    s  += __shfl_xor_sync(0xffffffffu, s,  o);
                    sq += __shfl_xor_sync(0xffffffffu, sq, o);
                }
                float mu  = s * (1.f / COUT);
                float var = sq * (1.f / COUT) - mu * mu;
                float rs  = rsqrtf(var + 1e-5f);
                int c = lane * 4;
                float4 r;
                r.x = (v.x - mu) * rs * sg[c + 0] + sbt[c + 0];
                r.y = (v.y - mu) * rs * sg[c + 1] + sbt[c + 1];
                r.z = (v.z - mu) * rs * sg[c + 2] + sbt[c + 2];
                r.w = (v.w - mu) * rs * sg[c + 3] + sbt[c + 3];
                atomicAdd(reinterpret_cast<float4*>(&out[(size_t)row * COUT + c]), r);
            } else {
                float2 v = *reinterpret_cast<const float2*>(&sF[e * P2 + lane * 2]);
                float s  = v.x + v.y;
                float sq = v.x * v.x + v.y * v.y;
                #pragma unroll
                for (int o = 16; o > 0; o >>= 1) {
                    s  += __shfl_xor_sync(0xffffffffu, s,  o);
                    sq += __shfl_xor_sync(0xffffffffu, sq, o);
                }
                float mu  = s * (1.f / COUT);
                float var = sq * (1.f / COUT) - mu * mu;
                float rs  = rsqrtf(var + 1e-5f);
                int c = lane * 2;
                float2 r;
                r.x = (v.x - mu) * rs * sg[c + 0] + sbt[c + 0];
                r.y = (v.y - mu) * rs * sg[c + 1] + sbt[c + 1];
                atomicAdd(reinterpret_cast<float2*>(&out[(size_t)row * COUT + c]), r);
            }
        }
    }
}

// ---------------------------------------------------------------------------
// out = leaky_relu(hb + cntA[n]*(cs+cb), 0.01)
__global__ void combine_kernel(float* __restrict__ out, const float* __restrict__ hb,
                               const int* __restrict__ cntA,
                               const float* __restrict__ cs, const float* __restrict__ cb) {
    const int c4n = CO / 4;
    int total = BDIM * NF * c4n;
    int i = blockIdx.x * blockDim.x + threadIdx.x;
    int stride = gridDim.x * blockDim.x;
    for (; i < total; i += stride) {
        int j4 = i % c4n;
        int n  = (i / c4n) % NF;
        float cnt = (float)cntA[n];
        float4 b = reinterpret_cast<const float4*>(hb)[i];
        float4 s = reinterpret_cast<const float4*>(cs)[j4];
        float4 t = reinterpret_cast<const float4*>(cb)[j4];
        float4 r;
        r.x = b.x + cnt * (s.x + t.x); r.x = r.x > 0.f ? r.x : 0.01f * r.x;
        r.y = b.y + cnt * (s.y + t.y); r.y = r.y > 0.f ? r.y : 0.01f * r.y;
        r.z = b.z + cnt * (s.z + t.z); r.z = r.z > 0.f ? r.z : 0.01f * r.z;
        r.w = b.w + cnt * (s.w + t.w); r.w = r.w > 0.f ? r.w : 0.01f * r.w;
        reinterpret_cast<float4*>(out)[i] = r;
    }
}

// ---------------------------------------------------------------------------
static constexpr int smem_bytes(int CIN, int COUT) {
    int K1 = 2 * CIN, P1 = K1 + 1, P2 = COUT + 4;
    int PF = (P1 > P2) ? P1 : P2;
    return (K1 * COUT + COUT * COUT + 4 * COUT + 32 * PF) * 4 + 32 * 4;
}

extern "C" void kernel_launch(void* const* d_in, const int* in_sizes, int n_in,
                              void* d_out, int out_size) {
    (void)in_sizes; (void)n_in; (void)out_size;
    const float* x    = (const float*)d_in[0];
    const int*   idx  = (const int*)d_in[1];
    const int*   ei_c = (const int*)d_in[2];
    const int*   ei_f = (const int*)d_in[3];
    const float* sW1 = (const float*)d_in[4];
    const float* sb1 = (const float*)d_in[5];
    const float* sW2 = (const float*)d_in[6];
    const float* sb2 = (const float*)d_in[7];
    const float* sg  = (const float*)d_in[8];
    const float* sbt = (const float*)d_in[9];
    const float* aW1 = (const float*)d_in[10];
    const float* ab1 = (const float*)d_in[11];
    const float* aW2 = (const float*)d_in[12];
    const float* ab2 = (const float*)d_in[13];
    const float* ag  = (const float*)d_in[14];
    const float* abt = (const float*)d_in[15];
    const float* bW1 = (const float*)d_in[16];
    const float* bb1 = (const float*)d_in[17];
    const float* bW2 = (const float*)d_in[18];
    const float* bb2 = (const float*)d_in[19];
    const float* bg  = (const float*)d_in[20];
    const float* bbt = (const float*)d_in[21];
    float* out = (float*)d_out;

    float *xf, *hb, *ha, *haf, *cs, *cb, *w1s, *w1a, *w1b;
    unsigned char* mask;
    int *cntA, *csrc, *cdst;
    cudaGetSymbolAddress((void**)&xf,   g_xf);
    cudaGetSymbolAddress((void**)&hb,   g_hb);
    cudaGetSymbolAddress((void**)&ha,   g_ha);
    cudaGetSymbolAddress((void**)&haf,  g_haf);
    cudaGetSymbolAddress((void**)&mask, g_mask);
    cudaGetSymbolAddress((void**)&cntA, g_cntA);
    cudaGetSymbolAddress((void**)&csrc, g_csrc);
    cudaGetSymbolAddress((void**)&cdst, g_cdst);
    cudaGetSymbolAddress((void**)&cs,   g_cs);
    cudaGetSymbolAddress((void**)&cb,   g_cb);
    cudaGetSymbolAddress((void**)&w1s,  g_w1s);
    cudaGetSymbolAddress((void**)&w1a,  g_w1a);
    cudaGetSymbolAddress((void**)&w1b,  g_w1b);
    int* ncomp = cntA + NF;

    constexpr int SM_S = smem_bytes(128, 128);  // 231680
    constexpr int SM_A = smem_bytes(128, 64);   // 117184
    constexpr int SM_B = smem_bytes(64, 128);   // 150528
    cudaFuncSetAttribute(edgeconv_kernel<128, 128, true>,
                         cudaFuncAttributeMaxDynamicSharedMemorySize, SM_S);
    cudaFuncSetAttribute(edgeconv_kernel<128, 64, false>,
                         cudaFuncAttributeMaxDynamicSharedMemorySize, SM_A);
    cudaFuncSetAttribute(edgeconv_kernel<64, 128, true>,
                         cudaFuncAttributeMaxDynamicSharedMemorySize, SM_B);

    // Zero accumulators + classification state
    zero_kernel<<<512, 256>>>((float4*)hb,  BDIM * NF * CO / 4);
    zero_kernel<<<128, 256>>>((float4*)ha,  BDIM * NC * 64 / 4);
    zero_kernel<<<32, 256>>>((float4*)cntA, (NF + 16) / 4);

    // Classification + weight prep
    mask_kernel<<<NC / 256, 256>>>(idx, mask);
    classify_kernel<<<EF / 256, 256>>>(ei_f, mask, cntA, csrc, cdst, ncomp);
    constvec_kernel<<<1, CO>>>(sb1, sW2, sb2, sg, sbt, cs);
    constvec_kernel<<<1, CO>>>(bb1, bW2, bb2, bg, bbt, cb);
    prepW1_kernel<<<(CI * CO + 255) / 256, 256>>>(sW1, w1s, CI, CO);
    prepW1_kernel<<<(CI * 64 + 255) / 256, 256>>>(aW1, w1a, CI, 64);
    prepW1_kernel<<<(64 * CO + 255) / 256, 256>>>(bW1, w1b, 64, CO);

    // xf = unpool(x)
    unpool_kernel<128><<<1024, 256>>>(x, xf, idx, NC, NF);

    // skip-conv -> hb
    edgeconv_kernel<128, 128, true><<<148, 256, SM_S>>>(
        xf, csrc, cdst, w1s, sb1, sW2, sb2, sg, sbt, hb, 0, NF, ncomp);

    // a-conv -> ha
    edgeconv_kernel<128, 64, false><<<148, 256, SM_A>>>(
        x, ei_c, ei_c + EC, w1a, ab1, aW2, ab2, ag, abt, ha, EC, NC, nullptr);

    // haf = unpool(ha)
    unpool_kernel<64><<<512, 256>>>(ha, haf, idx, NC, NF);

    // b-conv -> hb (accumulates on top of skip)
    edgeconv_kernel<64, 128, true><<<148, 256, SM_B>>>(
        haf, csrc, cdst, w1b, bb1, bW2, bb2, bg, bbt, hb, 0, NF, ncomp);

    // out = leaky_relu(hb + cntA*(cs+cb))
    combine_kernel<<<512, 256>>>(out, hb, cntA, cs, cb);
}

// round 4
// speedup vs baseline: 4.6262x; 1.8910x over previous
#include <cuda_runtime.h>
#include <cstdint>

// Problem constants
static constexpr int BDIM = 2;
static constexpr int NC   = 16384;
static constexpr int NF   = 65536;
static constexpr int CI   = 128;
static constexpr int CO   = 128;
static constexpr int EC   = 65536;
static constexpr int EF   = 262144;
static constexpr int MROW = BDIM * NC;   // 32768 coarse rows

// Scratch (device globals; zero-initialized at module load)
__device__ float g_hb [(size_t)BDIM * NF * CO];        // s+b conv accumulator
__device__ float g_ha [(size_t)BDIM * NC * (CO / 2)];  // a-conv accumulator
__device__ int   g_invmap[NF];                         // fine -> coarse (or -1)
__device__ int   g_cntA[NF + 16];                      // [NF] = nComp
__device__ int   g_csrcC[EF];                          // compacted: coarse src (-1 ok)
__device__ int   g_cdstC[EF];                          // compacted: coarse dst (-1 ok)
__device__ int   g_cdstF[EF];                          // compacted: fine dst
__device__ float g_cs[CO];
__device__ float g_cb[CO];
__device__ float g_w1s[2 * CI * CO];                   // [W1a-W1b ; W1b] (s)
__device__ float g_w1a[2 * CI * (CO / 2)];
__device__ float g_w1b[CO * CO];                       // (64*2) x 128
__device__ float g_Ps[(size_t)MROW * CO];
__device__ float g_Qs[(size_t)MROW * CO];
__device__ float g_Pa[(size_t)MROW * (CO / 2)];
__device__ float g_Qa[(size_t)MROW * (CO / 2)];
__device__ float g_Pb[(size_t)MROW * CO];
__device__ float g_Qb[(size_t)MROW * CO];

// ---------------------------------------------------------------------------
typedef unsigned long long u64;
__device__ __forceinline__ u64 pk2(float x) {
    u64 r; asm("mov.b64 %0,{%1,%1};" : "=l"(r) : "f"(x)); return r;
}
__device__ __forceinline__ void up2(u64 v, float& x, float& y) {
    asm("mov.b64 {%0,%1},%2;" : "=f"(x), "=f"(y) : "l"(v));
}
__device__ __forceinline__ u64 fma2(u64 a, u64 b, u64 c) {
    u64 d; asm("fma.rn.f32x2 %0,%1,%2,%3;" : "=l"(d) : "l"(a), "l"(b), "l"(c)); return d;
}

// ---------------------------------------------------------------------------
__global__ void zero_kernel(float4* __restrict__ p, int n4) {
    int i = blockIdx.x * blockDim.x + threadIdx.x;
    int stride = gridDim.x * blockDim.x;
    float4 z = make_float4(0.f, 0.f, 0.f, 0.f);
    for (; i < n4; i += stride) p[i] = z;
}

__global__ void neg1_kernel(int4* __restrict__ p, int n4) {
    int i = blockIdx.x * blockDim.x + threadIdx.x;
    int stride = gridDim.x * blockDim.x;
    int4 m = make_int4(-1, -1, -1, -1);
    for (; i < n4; i += stride) p[i] = m;
}

__global__ void invmap_kernel(const int* __restrict__ idx, int* __restrict__ invmap) {
    int i = blockIdx.x * blockDim.x + threadIdx.x;
    if (i < NC) invmap[idx[i]] = i;
}

__global__ void classify_kernel(const int* __restrict__ ei, const int* __restrict__ invmap,
                                int* __restrict__ cntA, int* __restrict__ csrcC,
                                int* __restrict__ cdstC, int* __restrict__ cdstF,
                                int* __restrict__ ncomp) {
    int e = blockIdx.x * blockDim.x + threadIdx.x;
    if (e >= EF) return;
    int s = ei[e], d = ei[EF + e];
    int sc = invmap[s], dc = invmap[d];
    if (sc < 0 && dc < 0) {
        atomicAdd(&cntA[d], 1);
    } else {
        unsigned act = __activemask();
        int lane = threadIdx.x & 31;
        int rank = __popc(act & ((1u << lane) - 1));
        int leader = __ffs(act) - 1;
        int base = 0;
        if (lane == leader) base = atomicAdd(ncomp, __popc(act));
        base = __shfl_sync(act, base, leader);
        csrcC[base + rank] = sc;
        cdstC[base + rank] = dc;
        cdstF[base + rank] = d;
    }
}

// W1t: rows [0,cin) = W1a - W1b ; rows [cin,2cin) = W1b
__global__ void prepW1_kernel(const float* __restrict__ W1, float* __restrict__ W1t,
                              int cin, int cout) {
    int i = blockIdx.x * blockDim.x + threadIdx.x;
    int n = cin * cout;
    if (i >= n) return;
    float top = W1[i];
    float bot = W1[n + i];
    W1t[i]     = top - bot;
    W1t[n + i] = bot;
}

__global__ void constvec_kernel(const float* __restrict__ b1, const float* __restrict__ W2,
                                const float* __restrict__ b2, const float* __restrict__ g,
                                const float* __restrict__ bt, float* __restrict__ c) {
    int j = threadIdx.x;  // CO threads
    float acc = b2[j];
    #pragma unroll 4
    for (int k = 0; k < CO; k++) acc += fmaxf(b1[k], 0.f) * W2[k * CO + j];
    __shared__ float rs_[4], rq_[4];
    float s = acc, qv = acc * acc;
    #pragma unroll
    for (int o = 16; o; o >>= 1) {
        s  += __shfl_xor_sync(0xffffffffu, s, o);
        qv += __shfl_xor_sync(0xffffffffu, qv, o);
    }
    int warp = j >> 5, lane = j & 31;
    if (lane == 0) { rs_[warp] = s; rq_[warp] = qv; }
    __syncthreads();
    float S = 0.f, Q = 0.f;
    #pragma unroll
    for (int w = 0; w < 4; w++) { S += rs_[w]; Q += rq_[w]; }
    float mu  = S * (1.f / CO);
    float var = Q * (1.f / CO) - mu * mu;
    c[j] = (acc - mu) * rsqrtf(var + 1e-5f) * g[j] + bt[j];
}

// ---------------------------------------------------------------------------
// Node-level GEMM: R[M, COUT] = X[M, K] @ W[K, COUT]. One 32-row tile per block.
template <int K, int COUT>
__global__ void __launch_bounds__(256, 2)
nodegemm_kernel(const float* __restrict__ X, const float* __restrict__ W,
                float* __restrict__ R) {
    constexpr int PX  = K + 1;
    constexpr int JT  = COUT / 16;
    constexpr int JT2 = JT / 2;
    constexpr int NXU = K / 32;

    extern __shared__ float sm[];
    float* sW = sm;             // K*COUT
    float* sX = sW + K * COUT;  // 32*PX

    const int tid = threadIdx.x;
    const int m0  = blockIdx.x * 32;

    for (int i = tid; i < (K * COUT) / 4; i += 256)
        reinterpret_cast<float4*>(sW)[i] = reinterpret_cast<const float4*>(W)[i];
    {
        int row = tid >> 3, sub = tid & 7;
        const float4* xr = reinterpret_cast<const float4*>(X + (size_t)(m0 + row) * K);
        #pragma unroll
        for (int u = 0; u < NXU; u++) {
            float4 v = xr[sub + 8 * u];
            float* d = sX + row * PX + (sub + 8 * u) * 4;
            d[0] = v.x; d[1] = v.y; d[2] = v.z; d[3] = v.w;
        }
    }
    __syncthreads();

    const int eh = tid & 15, jg = tid >> 4, j0 = jg * JT;
    u64 acc[2][JT2];
    #pragma unroll
    for (int t = 0; t < JT2; t++) { acc[0][t] = 0ull; acc[1][t] = 0ull; }

    #pragma unroll 2
    for (int k = 0; k < K; ++k) {
        u64 w[JT2];
        if constexpr (JT2 == 4) {
            ulonglong2 w01 = *reinterpret_cast<const ulonglong2*>(&sW[k * COUT + j0]);
            ulonglong2 w23 = *reinterpret_cast<const ulonglong2*>(&sW[k * COUT + j0 + 4]);
            w[0] = w01.x; w[1] = w01.y; w[2] = w23.x; w[3] = w23.y;
        } else {
            ulonglong2 w01 = *reinterpret_cast<const ulonglong2*>(&sW[k * COUT + j0]);
            w[0] = w01.x; w[1] = w01.y;
        }
        u64 f0 = pk2(sX[eh * PX + k]);
        u64 f1 = pk2(sX[(eh + 16) * PX + k]);
        #pragma unroll
        for (int t = 0; t < JT2; t++) {
            acc[0][t] = fma2(f0, w[t], acc[0][t]);
            acc[1][t] = fma2(f1, w[t], acc[1][t]);
        }
    }

    #pragma unroll
    for (int i = 0; i < 2; i++) {
        float v[JT];
        #pragma unroll
        for (int t = 0; t < JT2; t++) up2(acc[i][t], v[2 * t], v[2 * t + 1]);
        float* rr = R + (size_t)(m0 + eh + 16 * i) * COUT + j0;
        #pragma unroll
        for (int t = 0; t < JT; t += 4)
            *reinterpret_cast<float4*>(rr + t) =
                make_float4(v[t], v[t + 1], v[t + 2], v[t + 3]);
    }
}

// ---------------------------------------------------------------------------
// Edge kernel: h1 = relu(P[dst]+Q[src]+b1); h2 = h1@W2+b2; LN; vector atomics.
// 256 threads, tile = 32 edges, 2 blocks/SM.
template <int COUT, bool NCOMP>
__global__ void __launch_bounds__(256, 2)
edgeconv_kernel(const float* __restrict__ P, const float* __restrict__ Q,
                const int* __restrict__ srcC, const int* __restrict__ dstC,
                const int* __restrict__ dstF,
                const float* __restrict__ b1, const float* __restrict__ W2,
                const float* __restrict__ b2, const float* __restrict__ gam,
                const float* __restrict__ bet,
                float* __restrict__ out, int E, int NOUT,
                const int* __restrict__ ncomp) {
    constexpr int P2  = COUT + 4;
    constexpr int NE  = 32;
    constexpr int JT  = COUT / 16;
    constexpr int JT2 = JT / 2;
    constexpr int NU  = COUT / 32;   // float4 chunks per thread per half

    extern __shared__ float sm[];
    float* sW2 = sm;                  // COUT*COUT
    float* sb1 = sW2 + COUT * COUT;
    float* sb2 = sb1 + COUT;
    float* sg  = sb2 + COUT;
    float* sbt = sg + COUT;
    float* sF  = sbt + COUT;          // NE*P2 (h1, then h2 aliased)
    int*  sdst = (int*)(sF + NE * P2);

    const int tid  = threadIdx.x;
    const int lane = tid & 31;
    const int warp = tid >> 5;
    const int ge   = tid >> 3;        // edge 0..31
    const int sub  = tid & 7;         // 8 threads per edge
    const int eh   = tid & 15;
    const int jg   = tid >> 4;
    const int j0   = jg * JT;

    for (int i = tid; i < (COUT * COUT) / 4; i += 256)
        reinterpret_cast<float4*>(sW2)[i] = reinterpret_cast<const float4*>(W2)[i];
    if (tid < COUT) {
        sb1[tid] = b1[tid]; sb2[tid] = b2[tid];
        sg[tid]  = gam[tid]; sbt[tid] = bet[tid];
    }

    int Eeff = NCOMP ? *ncomp : E;
    const int total  = 2 * Eeff;
    const int ntiles = (total + NE - 1) / NE;

    float4 pfP[NU], pfQ[NU];
    int pdst = -1;

    auto fetch = [&](int tile) {
        pdst = -1;
        #pragma unroll
        for (int u = 0; u < NU; u++) {
            pfP[u] = make_float4(0.f, 0.f, 0.f, 0.f);
            pfQ[u] = make_float4(0.f, 0.f, 0.f, 0.f);
        }
        int gi = tile * NE + ge;
        if (tile < ntiles && gi < total) {
            int bb = (gi >= Eeff) ? 1 : 0;
            int ee = gi - bb * Eeff;
            int sc = srcC[ee];
            int dc = dstC[ee];
            int df = dstF[ee];
            pdst = bb * NOUT + df;
            if (dc >= 0) {
                const float4* pr = reinterpret_cast<const float4*>(
                    P + (size_t)(bb * NC + dc) * COUT);
                #pragma unroll
                for (int u = 0; u < NU; u++) pfP[u] = pr[sub + 8 * u];
            }
            if (sc >= 0) {
                const float4* qr = reinterpret_cast<const float4*>(
                    Q + (size_t)(bb * NC + sc) * COUT);
                #pragma unroll
                for (int u = 0; u < NU; u++) pfQ[u] = qr[sub + 8 * u];
            }
        }
    };

    fetch(blockIdx.x);

    for (int tile = blockIdx.x; tile < ntiles; tile += gridDim.x) {
        __syncthreads();  // S1: previous tile's LN finished

        // ---- h1 = relu(P + Q + b1) ----
        {
            float* frow = sF + ge * P2;
            #pragma unroll
            for (int u = 0; u < NU; u++) {
                int c4 = sub + 8 * u;
                float4 b = reinterpret_cast<const float4*>(sb1)[c4];
                float4 h;
                h.x = fmaxf(pfP[u].x + pfQ[u].x + b.x, 0.f);
                h.y = fmaxf(pfP[u].y + pfQ[u].y + b.y, 0.f);
                h.z = fmaxf(pfP[u].z + pfQ[u].z + b.z, 0.f);
                h.w = fmaxf(pfP[u].w + pfQ[u].w + b.w, 0.f);
                reinterpret_cast<float4*>(frow)[c4] = h;
            }
            if (sub == 0) sdst[ge] = pdst;
        }
        __syncthreads();  // S2

        // prefetch next tile (hides L2 gather under GEMM)
        fetch(tile + gridDim.x);

        // ---- h2 = h1 @ W2 + b2 ----
        u64 acc[2][JT2];
        #pragma unroll
        for (int t = 0; t < JT2; t++) {
            u64 bv = *reinterpret_cast<const u64*>(&sb2[j0 + 2 * t]);
            acc[0][t] = bv; acc[1][t] = bv;
        }
        #pragma unroll 2
        for (int k = 0; k < COUT; ++k) {
            u64 w[JT2];
            if constexpr (JT2 == 4) {
                ulonglong2 w01 = *reinterpret_cast<const ulonglong2*>(&sW2[k * COUT + j0]);
                ulonglong2 w23 = *reinterpret_cast<const ulonglong2*>(&sW2[k * COUT + j0 + 4]);
                w[0] = w01.x; w[1] = w01.y; w[2] = w23.x; w[3] = w23.y;
            } else {
                ulonglong2 w01 = *reinterpret_cast<const ulonglong2*>(&sW2[k * COUT + j0]);
                w[0] = w01.x; w[1] = w01.y;
            }
            u64 f0 = pk2(sF[eh * P2 + k]);
            u64 f1 = pk2(sF[(eh + 16) * P2 + k]);
            #pragma unroll
            for (int t = 0; t < JT2; t++) {
                acc[0][t] = fma2(f0, w[t], acc[0][t]);
                acc[1][t] = fma2(f1, w[t], acc[1][t]);
            }
        }
        __syncthreads();  // S3: h1 dead

        // ---- write h2 ----
        #pragma unroll
        for (int i = 0; i < 2; i++) {
            float v[JT];
            #pragma unroll
            for (int t = 0; t < JT2; t++) up2(acc[i][t], v[2 * t], v[2 * t + 1]);
            float* hrow = sF + (eh + 16 * i) * P2 + j0;
            #pragma unroll
            for (int t = 0; t < JT; t += 4)
                *reinterpret_cast<float4*>(hrow + t) =
                    make_float4(v[t], v[t + 1], v[t + 2], v[t + 3]);
        }
        __syncthreads();  // S4

        // ---- LayerNorm + vector atomic scatter (warp per edge) ----
        #pragma unroll
        for (int rr = 0; rr < 4; ++rr) {
            int e = warp + 8 * rr;
            int row = sdst[e];
            if (row < 0) continue;   // warp-uniform
            if constexpr (COUT == 128) {
                float4 v = *reinterpret_cast<const float4*>(&sF[e * P2 + lane * 4]);
                float s  = v.x + v.y + v.z + v.w;
                float sq = v.x * v.x + v.y * v.y + v.z * v.z + v.w * v.w;
                #pragma unroll
                for (int o = 16; o > 0; o >>= 1) {
                    s  += __shfl_xor_sync(0xffffffffu, s,  o);
                    sq += __shfl_xor_sync(0xffffffffu, sq, o);
                }
                float mu  = s * (1.f / COUT);
                float var = sq * (1.f / COUT) - mu * mu;
                float rs  = rsqrtf(var + 1e-5f);
                int c = lane * 4;
                float4 r;
                r.x = (v.x - mu) * rs * sg[c + 0] + sbt[c + 0];
                r.y = (v.y - mu) * rs * sg[c + 1] + sbt[c + 1];
                r.z = (v.z - mu) * rs * sg[c + 2] + sbt[c + 2];
                r.w = (v.w - mu) * rs * sg[c + 3] + sbt[c + 3];
                atomicAdd(reinterpret_cast<float4*>(&out[(size_t)row * COUT + c]), r);
            } else {
                float2 v = *reinterpret_cast<const float2*>(&sF[e * P2 + lane * 2]);
                float s  = v.x + v.y;
                float sq = v.x * v.x + v.y * v.y;
                #pragma unroll
                for (int o = 16; o > 0; o >>= 1) {
                    s  += __shfl_xor_sync(0xffffffffu, s,  o);
                    sq += __shfl_xor_sync(0xffffffffu, sq, o);
                }
                float mu  = s * (1.f / COUT);
                float var = sq * (1.f / COUT) - mu * mu;
                float rs  = rsqrtf(var + 1e-5f);
                int c = lane * 2;
                float2 r;
                r.x = (v.x - mu) * rs * sg[c + 0] + sbt[c + 0];
                r.y = (v.y - mu) * rs * sg[c + 1] + sbt[c + 1];
                atomicAdd(reinterpret_cast<float2*>(&out[(size_t)row * COUT + c]), r);
            }
        }
    }
}

// ---------------------------------------------------------------------------
// out = leaky_relu(hb + cntA[n]*(cs+cb), 0.01)
__global__ void combine_kernel(float* __restrict__ out, const float* __restrict__ hb,
                               const int* __restrict__ cntA,
                               const float* __restrict__ cs, const float* __restrict__ cb) {
    const int c4n = CO / 4;
    int total = BDIM * NF * c4n;
    int i = blockIdx.x * blockDim.x + threadIdx.x;
    int stride = gridDim.x * blockDim.x;
    for (; i < total; i += stride) {
        int j4 = i % c4n;
        int n  = (i / c4n) % NF;
        float cnt = (float)cntA[n];
        float4 b = reinterpret_cast<const float4*>(hb)[i];
        float4 s = reinterpret_cast<const float4*>(cs)[j4];
        float4 t = reinterpret_cast<const float4*>(cb)[j4];
        float4 r;
        r.x = b.x + cnt * (s.x + t.x); r.x = r.x > 0.f ? r.x : 0.01f * r.x;
        r.y = b.y + cnt * (s.y + t.y); r.y = r.y > 0.f ? r.y : 0.01f * r.y;
        r.z = b.z + cnt * (s.z + t.z); r.z = r.z > 0.f ? r.z : 0.01f * r.z;
        r.w = b.w + cnt * (s.w + t.w); r.w = r.w > 0.f ? r.w : 0.01f * r.w;
        reinterpret_cast<float4*>(out)[i] = r;
    }
}

// ---------------------------------------------------------------------------
static constexpr int edge_smem(int COUT) {
    return (COUT * COUT + 4 * COUT + 32 * (COUT + 4)) * 4 + 32 * 4;
}
static constexpr int ng_smem(int K, int COUT) {
    return (K * COUT + 32 * (K + 1)) * 4;
}

extern "C" void kernel_launch(void* const* d_in, const int* in_sizes, int n_in,
                              void* d_out, int out_size) {
    (void)in_sizes; (void)n_in; (void)out_size;
    const float* x    = (const float*)d_in[0];
    const int*   idx  = (const int*)d_in[1];
    const int*   ei_c = (const int*)d_in[2];
    const int*   ei_f = (const int*)d_in[3];
    const float* sW1 = (const float*)d_in[4];
    const float* sb1 = (const float*)d_in[5];
    const float* sW2 = (const float*)d_in[6];
    const float* sb2 = (const float*)d_in[7];
    const float* sg  = (const float*)d_in[8];
    const float* sbt = (const float*)d_in[9];
    const float* aW1 = (const float*)d_in[10];
    const float* ab1 = (const float*)d_in[11];
    const float* aW2 = (const float*)d_in[12];
    const float* ab2 = (const float*)d_in[13];
    const float* ag  = (const float*)d_in[14];
    const float* abt = (const float*)d_in[15];
    const float* bW1 = (const float*)d_in[16];
    const float* bb1 = (const float*)d_in[17];
    const float* bW2 = (const float*)d_in[18];
    const float* bb2 = (const float*)d_in[19];
    const float* bg  = (const float*)d_in[20];
    const float* bbt = (const float*)d_in[21];
    float* out = (float*)d_out;

    float *hb, *ha, *cs, *cb, *w1s, *w1a, *w1b;
    float *Ps, *Qs, *Pa, *Qa, *Pb, *Qb;
    int *invmap, *cntA, *csrcC, *cdstC, *cdstF;
    cudaGetSymbolAddress((void**)&hb,    g_hb);
    cudaGetSymbolAddress((void**)&ha,    g_ha);
    cudaGetSymbolAddress((void**)&invmap,g_invmap);
    cudaGetSymbolAddress((void**)&cntA,  g_cntA);
    cudaGetSymbolAddress((void**)&csrcC, g_csrcC);
    cudaGetSymbolAddress((void**)&cdstC, g_cdstC);
    cudaGetSymbolAddress((void**)&cdstF, g_cdstF);
    cudaGetSymbolAddress((void**)&cs,    g_cs);
    cudaGetSymbolAddress((void**)&cb,    g_cb);
    cudaGetSymbolAddress((void**)&w1s,   g_w1s);
    cudaGetSymbolAddress((void**)&w1a,   g_w1a);
    cudaGetSymbolAddress((void**)&w1b,   g_w1b);
    cudaGetSymbolAddress((void**)&Ps,    g_Ps);
    cudaGetSymbolAddress((void**)&Qs,    g_Qs);
    cudaGetSymbolAddress((void**)&Pa,    g_Pa);
    cudaGetSymbolAddress((void**)&Qa,    g_Qa);
    cudaGetSymbolAddress((void**)&Pb,    g_Pb);
    cudaGetSymbolAddress((void**)&Qb,    g_Qb);
    int* ncomp = cntA + NF;

    constexpr int ES128 = edge_smem(128);   // 84608
    constexpr int ES64  = edge_smem(64);    // 26240
    constexpr int NG_S  = ng_smem(128, 128);
    constexpr int NG_A  = ng_smem(128, 64);
    constexpr int NG_B  = ng_smem(64, 128);
    cudaFuncSetAttribute(edgeconv_kernel<128, true>,
                         cudaFuncAttributeMaxDynamicSharedMemorySize, ES128);
    cudaFuncSetAttribute(edgeconv_kernel<64, false>,
                         cudaFuncAttributeMaxDynamicSharedMemorySize, ES64);
    cudaFuncSetAttribute(nodegemm_kernel<128, 128>,
                         cudaFuncAttributeMaxDynamicSharedMemorySize, NG_S);
    cudaFuncSetAttribute(nodegemm_kernel<128, 64>,
                         cudaFuncAttributeMaxDynamicSharedMemorySize, NG_A);
    cudaFuncSetAttribute(nodegemm_kernel<64, 128>,
                         cudaFuncAttributeMaxDynamicSharedMemorySize, NG_B);

    // Reset state
    zero_kernel<<<512, 256>>>((float4*)hb,  BDIM * NF * CO / 4);
    zero_kernel<<<128, 256>>>((float4*)ha,  BDIM * NC * 64 / 4);
    zero_kernel<<<32, 256>>>((float4*)cntA, (NF + 16) / 4);
    neg1_kernel<<<64, 256>>>((int4*)invmap, NF / 4);

    // Index prep
    invmap_kernel<<<NC / 256, 256>>>(idx, invmap);
    classify_kernel<<<EF / 256, 256>>>(ei_f, invmap, cntA, csrcC, cdstC, cdstF, ncomp);

    // Weight prep + constant vectors
    constvec_kernel<<<1, CO>>>(sb1, sW2, sb2, sg, sbt, cs);
    constvec_kernel<<<1, CO>>>(bb1, bW2, bb2, bg, bbt, cb);
    prepW1_kernel<<<(CI * CO + 255) / 256, 256>>>(sW1, w1s, CI, CO);
    prepW1_kernel<<<(CI * 64 + 255) / 256, 256>>>(aW1, w1a, CI, 64);
    prepW1_kernel<<<(64 * CO + 255) / 256, 256>>>(bW1, w1b, 64, CO);

    // Node GEMMs for s and a (from x)
    nodegemm_kernel<128, 128><<<MROW / 32, 256, NG_S>>>(x, w1s, Ps);
    nodegemm_kernel<128, 128><<<MROW / 32, 256, NG_S>>>(x, w1s + CI * CO, Qs);
    nodegemm_kernel<128, 64><<<MROW / 32, 256, NG_A>>>(x, w1a, Pa);
    nodegemm_kernel<128, 64><<<MROW / 32, 256, NG_A>>>(x, w1a + CI * 64, Qa);

    // a-conv (coarse graph, all edges valid) -> ha
    edgeconv_kernel<64, false><<<296, 256, ES64>>>(
        Pa, Qa, ei_c, ei_c + EC, ei_c + EC,
        ab1, aW2, ab2, ag, abt, ha, EC, NC, nullptr);

    // Node GEMMs for b (from ha)
    nodegemm_kernel<64, 128><<<MROW / 32, 256, NG_B>>>(ha, w1b, Pb);
    nodegemm_kernel<64, 128><<<MROW / 32, 256, NG_B>>>(ha, w1b + 64 * CO, Qb);

    // skip-conv -> hb
    edgeconv_kernel<128, true><<<296, 256, ES128>>>(
        Ps, Qs, csrcC, cdstC, cdstF,
        sb1, sW2, sb2, sg, sbt, hb, 0, NF, ncomp);

    // b-conv -> hb (accumulates)
    edgeconv_kernel<128, true><<<296, 256, ES128>>>(
        Pb, Qb, csrcC, cdstC, cdstF,
        bb1, bW2, bb2, bg, bbt, hb, 0, NF, ncomp);

    // out = leaky_relu(hb + cntA*(cs+cb))
    combine_kernel<<<512, 256>>>(out, hb, cntA, cs, cb);
}

// round 5
// speedup vs baseline: 4.9313x; 1.0659x over previous
#include <cuda_runtime.h>
#include <cstdint>

// Problem constants
static constexpr int BDIM = 2;
static constexpr int NC   = 16384;
static constexpr int NF   = 65536;
static constexpr int CI   = 128;
static constexpr int CO   = 128;
static constexpr int EC   = 65536;
static constexpr int EF   = 262144;
static constexpr int MROW = BDIM * NC;   // 32768 coarse rows

// Scratch (device globals; zero-initialized at module load)
__device__ float g_hb [(size_t)BDIM * NF * CO];        // s+b conv accumulator
__device__ float g_ha [(size_t)BDIM * NC * (CO / 2)];  // a-conv accumulator
__device__ int   g_invmap[NF];                         // fine -> coarse (or -1)
__device__ int   g_cntA[NF + 16];                      // [NF] = nComp
__device__ int   g_csrcC[EF];                          // compacted: coarse src (-1 ok)
__device__ int   g_cdstC[EF];                          // compacted: coarse dst (-1 ok)
__device__ int   g_cdstF[EF];                          // compacted: fine dst
__device__ float g_cs[CO];
__device__ float g_cb[CO];
__device__ float g_w1s[2 * CI * CO];                   // [W1a-W1b ; W1b] (s)
__device__ float g_w1a[2 * CI * (CO / 2)];
__device__ float g_w1b[CO * CO];                       // (64*2) x 128
__device__ float g_Ps[(size_t)MROW * CO];
__device__ float g_Qs[(size_t)MROW * CO];
__device__ float g_Pa[(size_t)MROW * (CO / 2)];
__device__ float g_Qa[(size_t)MROW * (CO / 2)];
__device__ float g_Pb[(size_t)MROW * CO];
__device__ float g_Qb[(size_t)MROW * CO];

// ---------------------------------------------------------------------------
typedef unsigned long long u64;
__device__ __forceinline__ u64 pk2(float x) {
    u64 r; asm("mov.b64 %0,{%1,%1};" : "=l"(r) : "f"(x)); return r;
}
__device__ __forceinline__ void up2(u64 v, float& x, float& y) {
    asm("mov.b64 {%0,%1},%2;" : "=f"(x), "=f"(y) : "l"(v));
}
__device__ __forceinline__ u64 fma2(u64 a, u64 b, u64 c) {
    u64 d; asm("fma.rn.f32x2 %0,%1,%2,%3;" : "=l"(d) : "l"(a), "l"(b), "l"(c)); return d;
}

// ---------------------------------------------------------------------------
__global__ void zero_kernel(float4* __restrict__ p, int n4) {
    int i = blockIdx.x * blockDim.x + threadIdx.x;
    int stride = gridDim.x * blockDim.x;
    float4 z = make_float4(0.f, 0.f, 0.f, 0.f);
    for (; i < n4; i += stride) p[i] = z;
}

__global__ void neg1_kernel(int4* __restrict__ p, int n4) {
    int i = blockIdx.x * blockDim.x + threadIdx.x;
    int stride = gridDim.x * blockDim.x;
    int4 m = make_int4(-1, -1, -1, -1);
    for (; i < n4; i += stride) p[i] = m;
}

__global__ void invmap_kernel(const int* __restrict__ idx, int* __restrict__ invmap) {
    int i = blockIdx.x * blockDim.x + threadIdx.x;
    if (i < NC) invmap[idx[i]] = i;
}

__global__ void classify_kernel(const int* __restrict__ ei, const int* __restrict__ invmap,
                                int* __restrict__ cntA, int* __restrict__ csrcC,
                                int* __restrict__ cdstC, int* __restrict__ cdstF,
                                int* __restrict__ ncomp) {
    int e = blockIdx.x * blockDim.x + threadIdx.x;
    if (e >= EF) return;
    int s = ei[e], d = ei[EF + e];
    int sc = invmap[s], dc = invmap[d];
    if (sc < 0 && dc < 0) {
        atomicAdd(&cntA[d], 1);
    } else {
        unsigned act = __activemask();
        int lane = threadIdx.x & 31;
        int rank = __popc(act & ((1u << lane) - 1));
        int leader = __ffs(act) - 1;
        int base = 0;
        if (lane == leader) base = atomicAdd(ncomp, __popc(act));
        base = __shfl_sync(act, base, leader);
        csrcC[base + rank] = sc;
        cdstC[base + rank] = dc;
        cdstF[base + rank] = d;
    }
}

// W1t: rows [0,cin) = W1a - W1b ; rows [cin,2cin) = W1b
__global__ void prepW1_kernel(const float* __restrict__ W1, float* __restrict__ W1t,
                              int cin, int cout) {
    int i = blockIdx.x * blockDim.x + threadIdx.x;
    int n = cin * cout;
    if (i >= n) return;
    float top = W1[i];
    float bot = W1[n + i];
    W1t[i]     = top - bot;
    W1t[n + i] = bot;
}

__global__ void constvec_kernel(const float* __restrict__ b1, const float* __restrict__ W2,
                                const float* __restrict__ b2, const float* __restrict__ g,
                                const float* __restrict__ bt, float* __restrict__ c) {
    int j = threadIdx.x;  // CO threads
    float acc = b2[j];
    #pragma unroll 4
    for (int k = 0; k < CO; k++) acc += fmaxf(b1[k], 0.f) * W2[k * CO + j];
    __shared__ float rs_[4], rq_[4];
    float s = acc, qv = acc * acc;
    #pragma unroll
    for (int o = 16; o; o >>= 1) {
        s  += __shfl_xor_sync(0xffffffffu, s, o);
        qv += __shfl_xor_sync(0xffffffffu, qv, o);
    }
    int warp = j >> 5, lane = j & 31;
    if (lane == 0) { rs_[warp] = s; rq_[warp] = qv; }
    __syncthreads();
    float S = 0.f, Q = 0.f;
    #pragma unroll
    for (int w = 0; w < 4; w++) { S += rs_[w]; Q += rq_[w]; }
    float mu  = S * (1.f / CO);
    float var = Q * (1.f / CO) - mu * mu;
    c[j] = (acc - mu) * rsqrtf(var + 1e-5f) * g[j] + bt[j];
}

// ---------------------------------------------------------------------------
// Node-level GEMM: R[M, COUT] = X[M, K] @ W[K, COUT]. One 32-row tile per block.
template <int K, int COUT>
__global__ void __launch_bounds__(256, 2)
nodegemm_kernel(const float* __restrict__ X, const float* __restrict__ W,
                float* __restrict__ R) {
    constexpr int PX  = K + 1;
    constexpr int JT  = COUT / 16;
    constexpr int JT2 = JT / 2;
    constexpr int NXU = K / 32;

    extern __shared__ float sm[];
    float* sW = sm;             // K*COUT
    float* sX = sW + K * COUT;  // 32*PX

    const int tid = threadIdx.x;
    const int m0  = blockIdx.x * 32;

    for (int i = tid; i < (K * COUT) / 4; i += 256)
        reinterpret_cast<float4*>(sW)[i] = reinterpret_cast<const float4*>(W)[i];
    {
        int row = tid >> 3, sub = tid & 7;
        const float4* xr = reinterpret_cast<const float4*>(X + (size_t)(m0 + row) * K);
        #pragma unroll
        for (int u = 0; u < NXU; u++) {
            float4 v = xr[sub + 8 * u];
            float* d = sX + row * PX + (sub + 8 * u) * 4;
            d[0] = v.x; d[1] = v.y; d[2] = v.z; d[3] = v.w;
        }
    }
    __syncthreads();

    const int eh = tid & 15, jg = tid >> 4, j0 = jg * JT;
    u64 acc[2][JT2];
    #pragma unroll
    for (int t = 0; t < JT2; t++) { acc[0][t] = 0ull; acc[1][t] = 0ull; }

    #pragma unroll 2
    for (int k = 0; k < K; ++k) {
        u64 w[JT2];
        if constexpr (JT2 == 4) {
            ulonglong2 w01 = *reinterpret_cast<const ulonglong2*>(&sW[k * COUT + j0]);
            ulonglong2 w23 = *reinterpret_cast<const ulonglong2*>(&sW[k * COUT + j0 + 4]);
            w[0] = w01.x; w[1] = w01.y; w[2] = w23.x; w[3] = w23.y;
        } else {
            ulonglong2 w01 = *reinterpret_cast<const ulonglong2*>(&sW[k * COUT + j0]);
            w[0] = w01.x; w[1] = w01.y;
        }
        u64 f0 = pk2(sX[eh * PX + k]);
        u64 f1 = pk2(sX[(eh + 16) * PX + k]);
        #pragma unroll
        for (int t = 0; t < JT2; t++) {
            acc[0][t] = fma2(f0, w[t], acc[0][t]);
            acc[1][t] = fma2(f1, w[t], acc[1][t]);
        }
    }

    #pragma unroll
    for (int i = 0; i < 2; i++) {
        float v[JT];
        #pragma unroll
        for (int t = 0; t < JT2; t++) up2(acc[i][t], v[2 * t], v[2 * t + 1]);
        float* rr = R + (size_t)(m0 + eh + 16 * i) * COUT + j0;
        #pragma unroll
        for (int t = 0; t < JT; t += 4)
            *reinterpret_cast<float4*>(rr + t) =
                make_float4(v[t], v[t + 1], v[t + 2], v[t + 3]);
    }
}

// ---------------------------------------------------------------------------
// Edge kernel: h1 = relu(P[dst]+Q[src]+b1); h2 = h1@W2+b2; LN via per-thread
// partials; atomic float4 scatter directly from registers. 256 threads.
// COUT=128: 32-edge tiles; COUT=64: 64-edge tiles. 2 edges x 8 cols per thread.
template <int COUT, bool NCOMP>
__global__ void __launch_bounds__(256, 2)
edgeconv_kernel(const float* __restrict__ P, const float* __restrict__ Q,
                const int* __restrict__ srcC, const int* __restrict__ dstC,
                const int* __restrict__ dstF,
                const float* __restrict__ b1, const float* __restrict__ W2,
                const float* __restrict__ b2, const float* __restrict__ gam,
                const float* __restrict__ bet,
                float* __restrict__ out, int E, int NOUT,
                const int* __restrict__ ncomp) {
    constexpr int NE   = (COUT == 128) ? 32 : 64;   // edges per tile
    constexpr int EOFF = NE / 2;
    constexpr int P2   = COUT + 2;                  // LDS.64 feed: (P2/2) odd
    constexpr int TPE  = 256 / NE;                  // gather threads per edge
    constexpr int NJG  = 256 / EOFF;                // col groups (16 / 8)
    constexpr int PST  = NJG + 1;                   // partial pitch (float2)
    constexpr int JTU  = 4;                         // 4 u64 = 8 cols per thread
    constexpr int NU   = 4;                         // float4 gather per row

    extern __shared__ float sm[];
    float* sW2 = sm;                                // COUT*COUT
    float* sb1 = sW2 + COUT * COUT;
    float* sb2 = sb1 + COUT;
    float* sg  = sb2 + COUT;
    float* sbt = sg + COUT;
    float* sF  = sbt + COUT;                        // NE*P2 (h1)
    float* sPart = sF + NE * P2;                    // NE*PST float2
    int*  sdst = (int*)(sPart + NE * PST * 2);      // NE

    const int tid = threadIdx.x;
    const int ge  = tid / TPE;
    const int sub = tid % TPE;
    const int eh  = tid & (EOFF - 1);
    const int jg  = tid / EOFF;
    const int j0  = jg * 8;

    for (int i = tid; i < (COUT * COUT) / 4; i += 256)
        reinterpret_cast<float4*>(sW2)[i] = reinterpret_cast<const float4*>(W2)[i];
    if (tid < COUT) {
        sb1[tid] = b1[tid]; sb2[tid] = b2[tid];
        sg[tid]  = gam[tid]; sbt[tid] = bet[tid];
    }

    int Eeff = NCOMP ? *ncomp : E;
    const int total  = 2 * Eeff;
    const int ntiles = (total + NE - 1) / NE;

    float4 pfP[NU], pfQ[NU];
    int pdst = -1;

    auto fetch = [&](int tile) {
        pdst = -1;
        #pragma unroll
        for (int u = 0; u < NU; u++) {
            pfP[u] = make_float4(0.f, 0.f, 0.f, 0.f);
            pfQ[u] = make_float4(0.f, 0.f, 0.f, 0.f);
        }
        int gi = tile * NE + ge;
        if (tile < ntiles && gi < total) {
            int bb = (gi >= Eeff) ? 1 : 0;
            int ee = gi - bb * Eeff;
            int sc = srcC[ee];
            int dc = dstC[ee];
            int df = dstF[ee];
            pdst = bb * NOUT + df;
            if (dc >= 0) {
                const float4* pr = reinterpret_cast<const float4*>(
                    P + (size_t)(bb * NC + dc) * COUT);
                #pragma unroll
                for (int u = 0; u < NU; u++) pfP[u] = pr[sub + TPE * u];
            }
            if (sc >= 0) {
                const float4* qr = reinterpret_cast<const float4*>(
                    Q + (size_t)(bb * NC + sc) * COUT);
                #pragma unroll
                for (int u = 0; u < NU; u++) pfQ[u] = qr[sub + TPE * u];
            }
        }
    };

    fetch(blockIdx.x);

    for (int tile = blockIdx.x; tile < ntiles; tile += gridDim.x) {
        __syncthreads();  // S1: sF/sPart/sdst from previous tile fully consumed

        // ---- h1 = relu(P + Q + b1) -> sF ----
        {
            float2* frow = reinterpret_cast<float2*>(sF + ge * P2);
            #pragma unroll
            for (int u = 0; u < NU; u++) {
                int c4 = sub + TPE * u;
                float4 b = reinterpret_cast<const float4*>(sb1)[c4];
                frow[c4 * 2] = make_float2(fmaxf(pfP[u].x + pfQ[u].x + b.x, 0.f),
                                           fmaxf(pfP[u].y + pfQ[u].y + b.y, 0.f));
                frow[c4 * 2 + 1] = make_float2(fmaxf(pfP[u].z + pfQ[u].z + b.z, 0.f),
                                               fmaxf(pfP[u].w + pfQ[u].w + b.w, 0.f));
            }
            if (sub == 0) sdst[ge] = pdst;
        }
        __syncthreads();  // S2

        // prefetch next tile (hidden under GEMM)
        fetch(tile + gridDim.x);

        // ---- h2 = h1 @ W2 + b2 (2 edges x 8 cols per thread) ----
        u64 a0[JTU], a1[JTU];
        #pragma unroll
        for (int t = 0; t < JTU; t++) {
            u64 bv = *reinterpret_cast<const u64*>(&sb2[j0 + 2 * t]);
            a0[t] = bv; a1[t] = bv;
        }
        #pragma unroll 2
        for (int k = 0; k < COUT; k += 2) {
            u64 wa[JTU], wb[JTU];
            {
                ulonglong2 t0 = *reinterpret_cast<const ulonglong2*>(&sW2[k * COUT + j0]);
                ulonglong2 t1 = *reinterpret_cast<const ulonglong2*>(&sW2[k * COUT + j0 + 4]);
                wa[0] = t0.x; wa[1] = t0.y; wa[2] = t1.x; wa[3] = t1.y;
            }
            {
                ulonglong2 t0 = *reinterpret_cast<const ulonglong2*>(&sW2[(k + 1) * COUT + j0]);
                ulonglong2 t1 = *reinterpret_cast<const ulonglong2*>(&sW2[(k + 1) * COUT + j0 + 4]);
                wb[0] = t0.x; wb[1] = t0.y; wb[2] = t1.x; wb[3] = t1.y;
            }
            float2 f0 = *reinterpret_cast<const float2*>(&sF[eh * P2 + k]);
            float2 f1 = *reinterpret_cast<const float2*>(&sF[(eh + EOFF) * P2 + k]);
            u64 x0 = pk2(f0.x), x1 = pk2(f0.y);
            u64 y0 = pk2(f1.x), y1 = pk2(f1.y);
            #pragma unroll
            for (int t = 0; t < JTU; t++) {
                a0[t] = fma2(x0, wa[t], a0[t]);
                a0[t] = fma2(x1, wb[t], a0[t]);
                a1[t] = fma2(y0, wa[t], a1[t]);
                a1[t] = fma2(y1, wb[t], a1[t]);
            }
        }

        // ---- per-thread LN partials ----
        {
            float s0 = 0.f, q0 = 0.f, s1 = 0.f, q1 = 0.f;
            #pragma unroll
            for (int t = 0; t < JTU; t++) {
                float va, vb;
                up2(a0[t], va, vb); s0 += va + vb; q0 += va * va + vb * vb;
                up2(a1[t], va, vb); s1 += va + vb; q1 += va * va + vb * vb;
            }
            float2* pp = reinterpret_cast<float2*>(sPart);
            pp[eh * PST + jg]          = make_float2(s0, q0);
            pp[(eh + EOFF) * PST + jg] = make_float2(s1, q1);
        }
        __syncthreads();  // S3

        // ---- reduce partials, normalize in regs, atomic scatter ----
        #pragma unroll
        for (int i = 0; i < 2; i++) {
            int e = eh + EOFF * i;
            int row = sdst[e];
            const u64* acc = i ? a1 : a0;
            float s = 0.f, q = 0.f;
            const float2* pp = reinterpret_cast<const float2*>(sPart) + e * PST;
            #pragma unroll
            for (int t = 0; t < NJG; t++) { float2 v = pp[t]; s += v.x; q += v.y; }
            float mu  = s * (1.f / COUT);
            float var = q * (1.f / COUT) - mu * mu;
            float rs  = rsqrtf(var + 1e-5f);
            if (row >= 0) {
                float4 g0 = *reinterpret_cast<const float4*>(sg + j0);
                float4 g1 = *reinterpret_cast<const float4*>(sg + j0 + 4);
                float4 t0 = *reinterpret_cast<const float4*>(sbt + j0);
                float4 t1 = *reinterpret_cast<const float4*>(sbt + j0 + 4);
                float v0, v1, v2, v3, v4, v5, v6, v7;
                up2(acc[0], v0, v1); up2(acc[1], v2, v3);
                up2(acc[2], v4, v5); up2(acc[3], v6, v7);
                float4 r0, r1;
                r0.x = (v0 - mu) * rs * g0.x + t0.x;
                r0.y = (v1 - mu) * rs * g0.y + t0.y;
                r0.z = (v2 - mu) * rs * g0.z + t0.z;
                r0.w = (v3 - mu) * rs * g0.w + t0.w;
                r1.x = (v4 - mu) * rs * g1.x + t1.x;
                r1.y = (v5 - mu) * rs * g1.y + t1.y;
                r1.z = (v6 - mu) * rs * g1.z + t1.z;
                r1.w = (v7 - mu) * rs * g1.w + t1.w;
                float* op = &out[(size_t)row * COUT + j0];
                atomicAdd(reinterpret_cast<float4*>(op), r0);
                atomicAdd(reinterpret_cast<float4*>(op + 4), r1);
            }
        }
    }
}

// ---------------------------------------------------------------------------
// out = leaky_relu(hb + cntA[n]*(cs+cb), 0.01)
__global__ void combine_kernel(float* __restrict__ out, const float* __restrict__ hb,
                               const int* __restrict__ cntA,
                               const float* __restrict__ cs, const float* __restrict__ cb) {
    const int c4n = CO / 4;
    int total = BDIM * NF * c4n;
    int i = blockIdx.x * blockDim.x + threadIdx.x;
    int stride = gridDim.x * blockDim.x;
    for (; i < total; i += stride) {
        int j4 = i % c4n;
        int n  = (i / c4n) % NF;
        float cnt = (float)cntA[n];
        float4 b = reinterpret_cast<const float4*>(hb)[i];
        float4 s = reinterpret_cast<const float4*>(cs)[j4];
        float4 t = reinterpret_cast<const float4*>(cb)[j4];
        float4 r;
        r.x = b.x + cnt * (s.x + t.x); r.x = r.x > 0.f ? r.x : 0.01f * r.x;
        r.y = b.y + cnt * (s.y + t.y); r.y = r.y > 0.f ? r.y : 0.01f * r.y;
        r.z = b.z + cnt * (s.z + t.z); r.z = r.z > 0.f ? r.z : 0.01f * r.z;
        r.w = b.w + cnt * (s.w + t.w); r.w = r.w > 0.f ? r.w : 0.01f * r.w;
        reinterpret_cast<float4*>(out)[i] = r;
    }
}

// ---------------------------------------------------------------------------
static constexpr int edge_smem(int COUT) {
    int NE  = (COUT == 128) ? 32 : 64;
    int NJG = 256 / (NE / 2);
    return (COUT * COUT + 4 * COUT + NE * (COUT + 2) + NE * (NJG + 1) * 2) * 4 + NE * 4;
}
static constexpr int ng_smem(int K, int COUT) {
    return (K * COUT + 32 * (K + 1)) * 4;
}

extern "C" void kernel_launch(void* const* d_in, const int* in_sizes, int n_in,
                              void* d_out, int out_size) {
    (void)in_sizes; (void)n_in; (void)out_size;
    const float* x    = (const float*)d_in[0];
    const int*   idx  = (const int*)d_in[1];
    const int*   ei_c = (const int*)d_in[2];
    const int*   ei_f = (const int*)d_in[3];
    const float* sW1 = (const float*)d_in[4];
    const float* sb1 = (const float*)d_in[5];
    const float* sW2 = (const float*)d_in[6];
    const float* sb2 = (const float*)d_in[7];
    const float* sg  = (const float*)d_in[8];
    const float* sbt = (const float*)d_in[9];
    const float* aW1 = (const float*)d_in[10];
    const float* ab1 = (const float*)d_in[11];
    const float* aW2 = (const float*)d_in[12];
    const float* ab2 = (const float*)d_in[13];
    const float* ag  = (const float*)d_in[14];
    const float* abt = (const float*)d_in[15];
    const float* bW1 = (const float*)d_in[16];
    const float* bb1 = (const float*)d_in[17];
    const float* bW2 = (const float*)d_in[18];
    const float* bb2 = (const float*)d_in[19];
    const float* bg  = (const float*)d_in[20];
    const float* bbt = (const float*)d_in[21];
    float* out = (float*)d_out;

    float *hb, *ha, *cs, *cb, *w1s, *w1a, *w1b;
    float *Ps, *Qs, *Pa, *Qa, *Pb, *Qb;
    int *invmap, *cntA, *csrcC, *cdstC, *cdstF;
    cudaGetSymbolAddress((void**)&hb,    g_hb);
    cudaGetSymbolAddress((void**)&ha,    g_ha);
    cudaGetSymbolAddress((void**)&invmap,g_invmap);
    cudaGetSymbolAddress((void**)&cntA,  g_cntA);
    cudaGetSymbolAddress((void**)&csrcC, g_csrcC);
    cudaGetSymbolAddress((void**)&cdstC, g_cdstC);
    cudaGetSymbolAddress((void**)&cdstF, g_cdstF);
    cudaGetSymbolAddress((void**)&cs,    g_cs);
    cudaGetSymbolAddress((void**)&cb,    g_cb);
    cudaGetSymbolAddress((void**)&w1s,   g_w1s);
    cudaGetSymbolAddress((void**)&w1a,   g_w1a);
    cudaGetSymbolAddress((void**)&w1b,   g_w1b);
    cudaGetSymbolAddress((void**)&Ps,    g_Ps);
    cudaGetSymbolAddress((void**)&Qs,    g_Qs);
    cudaGetSymbolAddress((void**)&Pa,    g_Pa);
    cudaGetSymbolAddress((void**)&Qa,    g_Qa);
    cudaGetSymbolAddress((void**)&Pb,    g_Pb);
    cudaGetSymbolAddress((void**)&Qb,    g_Qb);
    int* ncomp = cntA + NF;

    constexpr int ES128 = edge_smem(128);
    constexpr int ES64  = edge_smem(64);
    constexpr int NG_S  = ng_smem(128, 128);
    constexpr int NG_A  = ng_smem(128, 64);
    constexpr int NG_B  = ng_smem(64, 128);
    cudaFuncSetAttribute(edgeconv_kernel<128, true>,
                         cudaFuncAttributeMaxDynamicSharedMemorySize, ES128);
    cudaFuncSetAttribute(edgeconv_kernel<64, false>,
                         cudaFuncAttributeMaxDynamicSharedMemorySize, ES64);
    cudaFuncSetAttribute(nodegemm_kernel<128, 128>,
                         cudaFuncAttributeMaxDynamicSharedMemorySize, NG_S);
    cudaFuncSetAttribute(nodegemm_kernel<128, 64>,
                         cudaFuncAttributeMaxDynamicSharedMemorySize, NG_A);
    cudaFuncSetAttribute(nodegemm_kernel<64, 128>,
                         cudaFuncAttributeMaxDynamicSharedMemorySize, NG_B);

    // Reset state
    zero_kernel<<<512, 256>>>((float4*)hb,  BDIM * NF * CO / 4);
    zero_kernel<<<128, 256>>>((float4*)ha,  BDIM * NC * 64 / 4);
    zero_kernel<<<32, 256>>>((float4*)cntA, (NF + 16) / 4);
    neg1_kernel<<<64, 256>>>((int4*)invmap, NF / 4);

    // Index prep
    invmap_kernel<<<NC / 256, 256>>>(idx, invmap);
    classify_kernel<<<EF / 256, 256>>>(ei_f, invmap, cntA, csrcC, cdstC, cdstF, ncomp);

    // Weight prep + constant vectors
    constvec_kernel<<<1, CO>>>(sb1, sW2, sb2, sg, sbt, cs);
    constvec_kernel<<<1, CO>>>(bb1, bW2, bb2, bg, bbt, cb);
    prepW1_kernel<<<(CI * CO + 255) / 256, 256>>>(sW1, w1s, CI, CO);
    prepW1_kernel<<<(CI * 64 + 255) / 256, 256>>>(aW1, w1a, CI, 64);
    prepW1_kernel<<<(64 * CO + 255) / 256, 256>>>(bW1, w1b, 64, CO);

    // Node GEMMs for s and a (from x)
    nodegemm_kernel<128, 128><<<MROW / 32, 256, NG_S>>>(x, w1s, Ps);
    nodegemm_kernel<128, 128><<<MROW / 32, 256, NG_S>>>(x, w1s + CI * CO, Qs);
    nodegemm_kernel<128, 64><<<MROW / 32, 256, NG_A>>>(x, w1a, Pa);
    nodegemm_kernel<128, 64><<<MROW / 32, 256, NG_A>>>(x, w1a + CI * 64, Qa);

    // a-conv (coarse graph, all edges valid) -> ha
    edgeconv_kernel<64, false><<<296, 256, ES64>>>(
        Pa, Qa, ei_c, ei_c + EC, ei_c + EC,
        ab1, aW2, ab2, ag, abt, ha, EC, NC, nullptr);

    // Node GEMMs for b (from ha)
    nodegemm_kernel<64, 128><<<MROW / 32, 256, NG_B>>>(ha, w1b, Pb);
    nodegemm_kernel<64, 128><<<MROW / 32, 256, NG_B>>>(ha, w1b + 64 * CO, Qb);

    // skip-conv -> hb
    edgeconv_kernel<128, true><<<296, 256, ES128>>>(
        Ps, Qs, csrcC, cdstC, cdstF,
        sb1, sW2, sb2, sg, sbt, hb, 0, NF, ncomp);

    // b-conv -> hb (accumulates)
    edgeconv_kernel<128, true><<<296, 256, ES128>>>(
        Pb, Qb, csrcC, cdstC, cdstF,
        bb1, bW2, bb2, bg, bbt, hb, 0, NF, ncomp);

    // out = leaky_relu(hb + cntA*(cs+cb))
    combine_kernel<<<512, 256>>>(out, hb, cntA, cs, cb);
}